// round 6
// baseline (speedup 1.0000x reference)
#include <cuda_runtime.h>
#include <cuda_bf16.h>
#include <math.h>
#include <cstdint>

#define Bb   32
#define Kk   64
#define Dd   256
#define LSs  128
#define NLl  2
#define Mm   (Bb*Kk)          // 2048 rows
#define QS   1024             // qkab row stride
#define GK   256              // GEMM K

// ---------------- scratch (no allocs allowed) ----------------
__device__ float g_x   [Mm*Dd];
__device__ float g_qkab[Mm*QS];
__device__ float g_hp  [Mm*Dd];
__device__ float g_bc  [4*Dd];
__device__ float g_s   [Bb*Dd];
// bf16 hi/lo duals
__device__ __nv_bfloat16 g_xh [Mm*Dd], g_xl [Mm*Dd];
__device__ __nv_bfloat16 g_ggh[Mm*Dd], g_ggl[Mm*Dd];
__device__ __nv_bfloat16 g_hh [Mm*Dd], g_hl [Mm*Dd];
__device__ __nv_bfloat16 g_th [Mm*Dd], g_tl [Mm*Dd];
__device__ __nv_bfloat16 g_wch[4*Dd*Dd], g_wcl[4*Dd*Dd];
__device__ __nv_bfloat16 g_w2h[3*Dd*Dd], g_w2l[3*Dd*Dd];

// ---------------- fast exact-enough gelu (A&S 7.1.26, |err| < 2e-7) ----------------
__device__ __forceinline__ float gelu_fast(float x) {
    float z = fabsf(x) * 0.7071067811865476f;
    float w = fmaf(z, 0.3275911f, 1.0f);
    float t;
    asm("rcp.approx.f32 %0, %1;" : "=f"(t) : "f"(w));
    float ez = __expf(-z * z);
    float p = fmaf(fmaf(fmaf(fmaf(1.061405429f, t, -1.453152027f), t,
                     1.421413741f), t, -0.284496736f), t, 0.254829592f) * t;
    float e = fmaf(-p, ez, 1.0f);                 // erf(|z|)
    float phi = fmaf(copysignf(e, x), 0.5f, 0.5f);
    return x * phi;
}

__device__ __forceinline__ uint32_t smem_u32(const void* p) {
    uint32_t a;
    asm("{ .reg .u64 t; cvta.to.shared.u64 t, %1; cvt.u32.u64 %0, t; }" : "=r"(a) : "l"(p));
    return a;
}

// split fp32 -> (hi, lo) bf16
__device__ __forceinline__ void split_bf16(float v, __nv_bfloat16& h, __nv_bfloat16& l) {
    h = __float2bfloat16(v);
    l = __float2bfloat16(v - __bfloat162float(h));
}
// pack pair (x0, x1) -> bf16x2 words for hi and lo
__device__ __forceinline__ void split_pair(float x0, float x1, uint32_t& hp, uint32_t& lp) {
    asm("cvt.rn.bf16x2.f32 %0, %1, %2;" : "=r"(hp) : "f"(x1), "f"(x0));
    float h0 = __uint_as_float(hp << 16);
    float h1 = __uint_as_float(hp & 0xffff0000u);
    asm("cvt.rn.bf16x2.f32 %0, %1, %2;" : "=r"(lp) : "f"(x1 - h1), "f"(x0 - h0));
}

// ---------------- warp MMA primitives ----------------
__device__ __forceinline__ void ldsm_x4(uint32_t* r, uint32_t addr) {
    asm volatile("ldmatrix.sync.aligned.m8n8.x4.shared.b16 {%0,%1,%2,%3}, [%4];"
        : "=r"(r[0]), "=r"(r[1]), "=r"(r[2]), "=r"(r[3]) : "r"(addr));
}
__device__ __forceinline__ void ldsm_x2(uint32_t* r, uint32_t addr) {
    asm volatile("ldmatrix.sync.aligned.m8n8.x2.shared.b16 {%0,%1}, [%2];"
        : "=r"(r[0]), "=r"(r[1]) : "r"(addr));
}
__device__ __forceinline__ void mma_bf16(float* c, const uint32_t* a, const uint32_t* b) {
    asm volatile("mma.sync.aligned.m16n8k16.row.col.f32.bf16.bf16.f32 "
        "{%0,%1,%2,%3}, {%4,%5,%6,%7}, {%8,%9}, {%0,%1,%2,%3};"
        : "+f"(c[0]), "+f"(c[1]), "+f"(c[2]), "+f"(c[3])
        : "r"(a[0]), "r"(a[1]), "r"(a[2]), "r"(a[3]), "r"(b[0]), "r"(b[1]));
}

// ---------------- smem layout for tc_gemm ----------------
#define LDSB  528
#define SM_AH 0
#define SM_AL (SM_AH + 128*LDSB)
#define SM_BH (SM_AL + 128*LDSB)
#define SM_BL (SM_BH + 64*LDSB)
#define SM_TOT (SM_BL + 64*LDSB)     // 202752 B

// stage pre-converted bf16 duals: pure uint4 copies
template<int ROWS>
__device__ __forceinline__ void stage_dual(const __nv_bfloat16* __restrict__ Gh,
                                           const __nv_bfloat16* __restrict__ Gl,
                                           char* smh, char* sml, int tid) {
    const int ngroups = ROWS * (GK / 8);
    for (int g = tid; g < ngroups; g += 256) {
        int row = g >> 5;
        int k0  = (g & 31) * 8;
        uint4 vh = *(const uint4*)(Gh + (size_t)row * GK + k0);
        uint4 vl = *(const uint4*)(Gl + (size_t)row * GK + k0);
        uint32_t off = (uint32_t)(row * LDSB + k0 * 2);
        *(uint4*)(smh + off) = vh;
        *(uint4*)(sml + off) = vl;
    }
}

// ---------------- bf16x3 GEMM: C = A[M,256] @ Bw[N,256]^T (+bias)(+gelu)(+resid) ----
// CTA: 128x64 tile, 8 warps (4M x 2N), warp tile 32x32.
// Cf (fp32, stride ldc) optional; Ch/Cl (bf16 duals, stride 256) optional.
__global__ void __launch_bounds__(256)
tc_gemm(const __nv_bfloat16* __restrict__ Ah, const __nv_bfloat16* __restrict__ Al,
        const __nv_bfloat16* __restrict__ Bh, const __nv_bfloat16* __restrict__ Bl,
        const float* __restrict__ bias, const float* __restrict__ resid,
        float* __restrict__ Cf, int ldc,
        __nv_bfloat16* __restrict__ Ch, __nv_bfloat16* __restrict__ Cl,
        int do_gelu)
{
    extern __shared__ char sm[];
    uint32_t smb = smem_u32(sm);
    const int tid = threadIdx.x, lane = tid & 31, wid = tid >> 5;
    const int warp_m = wid & 3, warp_n = wid >> 2;
    const int bm = blockIdx.y * 128, bn = blockIdx.x * 64;

    stage_dual<128>(Ah + (size_t)bm * GK, Al + (size_t)bm * GK, sm + SM_AH, sm + SM_AL, tid);
    stage_dual<64>( Bh + (size_t)bn * GK, Bl + (size_t)bn * GK, sm + SM_BH, sm + SM_BL, tid);
    __syncthreads();

    float acc[2][4][4];
    #pragma unroll
    for (int i = 0; i < 2; i++)
        #pragma unroll
        for (int j = 0; j < 4; j++)
            #pragma unroll
            for (int e = 0; e < 4; e++) acc[i][j][e] = 0.f;

    uint32_t a_base[2], b_base[4];
    #pragma unroll
    for (int tm = 0; tm < 2; tm++)
        a_base[tm] = smb + SM_AH
                   + (uint32_t)((warp_m * 32 + tm * 16 + (lane & 15)) * LDSB)
                   + (uint32_t)((lane >> 4) * 16);
    #pragma unroll
    for (int tn = 0; tn < 4; tn++)
        b_base[tn] = smb + SM_BH
                   + (uint32_t)((warp_n * 32 + tn * 8 + (lane & 7)) * LDSB)
                   + (uint32_t)(((lane >> 3) & 1) * 16);

    const uint32_t DA = SM_AL - SM_AH;
    const uint32_t DB = SM_BL - SM_BH;

    #pragma unroll
    for (int ks = 0; ks < 16; ks++) {
        const uint32_t kb = ks * 32;
        uint32_t ah[2][4], al[2][4], bh[4][2], bl[4][2];
        #pragma unroll
        for (int tm = 0; tm < 2; tm++) {
            ldsm_x4(ah[tm], a_base[tm] + kb);
            ldsm_x4(al[tm], a_base[tm] + kb + DA);
        }
        #pragma unroll
        for (int tn = 0; tn < 4; tn++) {
            ldsm_x2(bh[tn], b_base[tn] + kb);
            ldsm_x2(bl[tn], b_base[tn] + kb + DB);
        }
        #pragma unroll
        for (int tm = 0; tm < 2; tm++)
            #pragma unroll
            for (int tn = 0; tn < 4; tn++) {
                mma_bf16(acc[tm][tn], ah[tm], bh[tn]);
                mma_bf16(acc[tm][tn], ah[tm], bl[tn]);
                mma_bf16(acc[tm][tn], al[tm], bh[tn]);
            }
    }

    #pragma unroll
    for (int tm = 0; tm < 2; tm++) {
        int r0 = bm + warp_m * 32 + tm * 16 + (lane >> 2);
        #pragma unroll
        for (int tn = 0; tn < 4; tn++) {
            int c = bn + warp_n * 32 + tn * 8 + (lane & 3) * 2;
            #pragma unroll
            for (int h = 0; h < 2; h++) {
                int r = r0 + h * 8;
                float x0 = acc[tm][tn][h * 2 + 0];
                float x1 = acc[tm][tn][h * 2 + 1];
                if (bias)  { x0 += bias[c]; x1 += bias[c + 1]; }
                if (do_gelu) { x0 = gelu_fast(x0); x1 = gelu_fast(x1); }
                if (resid) {
                    float2 rr = *(const float2*)(resid + (size_t)r * ldc + c);
                    x0 += rr.x; x1 += rr.y;
                }
                if (Cf) *(float2*)(Cf + (size_t)r * ldc + c) = make_float2(x0, x1);
                if (Ch) {
                    uint32_t hp, lp;
                    split_pair(x0, x1, hp, lp);
                    *(uint32_t*)(Ch + (size_t)r * Dd + c) = hp;
                    *(uint32_t*)(Cl + (size_t)r * Dd + c) = lp;
                }
            }
        }
    }
}

// ---------------- producer/conversion kernels ----------------
__global__ void copy_conv_kernel(const float* __restrict__ src, float* __restrict__ dst,
                                 __nv_bfloat16* __restrict__ dh, __nv_bfloat16* __restrict__ dl,
                                 int n) {
    int i = blockIdx.x * blockDim.x + threadIdx.x;
    if (i < n) {
        float v = src[i];
        dst[i] = v;
        __nv_bfloat16 h, l; split_bf16(v, h, l);
        dh[i] = h; dl[i] = l;
    }
}

// pack combined weights (duals): rows [0:256)=k_w, [256:512)=q_w, [512:768)=W1a+W1b, [768:1024)=W1b
__global__ void pack_kernel(const float* __restrict__ kw, const float* __restrict__ qw,
                            const float* __restrict__ w1, const float* __restrict__ rb1,
                            __nv_bfloat16* __restrict__ wch, __nv_bfloat16* __restrict__ wcl,
                            float* __restrict__ bc) {
    int i = blockIdx.x * blockDim.x + threadIdx.x;
    int r = i >> 8, c = i & 255;
    float v;
    if (r < 256)      v = kw[r * Dd + c];
    else if (r < 512) v = qw[(r - 256) * Dd + c];
    else if (r < 768) { int d = r - 512; v = w1[d * 2 * Dd + c] + w1[d * 2 * Dd + Dd + c]; }
    else              { int d = r - 768; v = w1[d * 2 * Dd + Dd + c]; }
    __nv_bfloat16 h, l; split_bf16(v, h, l);
    wch[i] = h; wcl[i] = l;
    if (i < 4 * Dd) bc[i] = (i >= 512 && i < 768) ? rb1[i - 512] : 0.f;
}

// pack rw2|mw1|mw2 as dual slabs
__global__ void w2pack_kernel(const float* __restrict__ rw2, const float* __restrict__ mw1,
                              const float* __restrict__ mw2,
                              __nv_bfloat16* __restrict__ w2h, __nv_bfloat16* __restrict__ w2l) {
    int i = blockIdx.x * blockDim.x + threadIdx.x;   // [0, 3*65536)
    int s = i >> 16, o = i & 65535;
    const float* src = (s == 0) ? rw2 : ((s == 1) ? mw1 : mw2);
    float v = src[o];
    __nv_bfloat16 h, l; split_bf16(v, h, l);
    w2h[i] = h; w2l[i] = l;
}

// ---------------- attention + gelu aggregation, 4 queries per block ----------------
// qkab row layout: [k(256) | q(256) | a(256) | bb(256)]
__global__ void __launch_bounds__(256)
attn_kernel(const float* __restrict__ qkab,
            __nv_bfloat16* __restrict__ ggh, __nv_bfloat16* __restrict__ ggl)
{
    const int b = blockIdx.y, i0 = blockIdx.x * 4;
    const int tid = threadIdx.x;
    const int lane = tid & 31, warp = tid >> 5;

    __shared__ float sq[4][Dd];
    __shared__ float sa[4][Dd];
    __shared__ float sl[4][Kk];
    __shared__ float sp[4][Kk];

    const float* base = qkab + (size_t)b * Kk * QS;

    #pragma unroll
    for (int ii = 0; ii < 4; ii++) {
        const float* row = base + (size_t)(i0 + ii) * QS;
        sq[ii][tid] = row[256 + tid];
        sa[ii][tid] = row[512 + tid];
    }
    __syncthreads();

    // logits: warp handles j, computes dots for all 4 queries (k loaded once)
    for (int j = warp; j < Kk; j += 8) {
        const float* kj = base + (size_t)j * QS;
        float kv[8];
        #pragma unroll
        for (int m = 0; m < 8; m++) kv[m] = kj[lane + 32 * m];
        #pragma unroll
        for (int ii = 0; ii < 4; ii++) {
            float t = 0.f;
            #pragma unroll
            for (int m = 0; m < 8; m++) t = fmaf(sq[ii][lane + 32 * m], kv[m], t);
            #pragma unroll
            for (int o = 16; o; o >>= 1) t += __shfl_xor_sync(0xffffffffu, t, o);
            if (lane == 0) sl[ii][j] = t * 0.0625f;   // D^-0.5
        }
    }
    __syncthreads();

    // 4 softmaxes: warp w < 4 handles query w
    if (warp < 4) {
        float v0 = sl[warp][lane], v1 = sl[warp][lane + 32];
        float m = fmaxf(v0, v1);
        #pragma unroll
        for (int o = 16; o; o >>= 1) m = fmaxf(m, __shfl_xor_sync(0xffffffffu, m, o));
        float e0 = __expf(v0 - m), e1 = __expf(v1 - m);
        float s = e0 + e1;
        #pragma unroll
        for (int o = 16; o; o >>= 1) s += __shfl_xor_sync(0xffffffffu, s, o);
        float inv = 1.f / s;
        sp[warp][lane] = e0 * inv; sp[warp][lane + 32] = e1 * inv;
    }
    __syncthreads();

    // aggregation: thread owns dim d = tid; bb loaded once, 4 gelu per j
    const float a0 = sa[0][tid], a1 = sa[1][tid], a2 = sa[2][tid], a3 = sa[3][tid];
    float c0 = 0.f, c1 = 0.f, c2 = 0.f, c3 = 0.f;
    const float* bbp = base + 768 + tid;
    #pragma unroll 4
    for (int j = 0; j < Kk; j++) {
        float bb = __ldg(bbp + (size_t)j * QS);
        c0 = fmaf(sp[0][j], gelu_fast(a0 - bb), c0);
        c1 = fmaf(sp[1][j], gelu_fast(a1 - bb), c1);
        c2 = fmaf(sp[2][j], gelu_fast(a2 - bb), c2);
        c3 = fmaf(sp[3][j], gelu_fast(a3 - bb), c3);
    }
    float cc[4] = {c0, c1, c2, c3};
    #pragma unroll
    for (int ii = 0; ii < 4; ii++) {
        size_t idx = (size_t)(b * Kk + i0 + ii) * Dd + tid;
        __nv_bfloat16 h, l; split_bf16(cc[ii], h, l);
        ggh[idx] = h; ggl[idx] = l;
    }
}

// ---------------- layernorm over D=256 -> duals only ----------------
__device__ __forceinline__ float blocksum256(float v, float* red) {
    int lane = threadIdx.x & 31, w = threadIdx.x >> 5;
    #pragma unroll
    for (int o = 16; o; o >>= 1) v += __shfl_xor_sync(0xffffffffu, v, o);
    __syncthreads();
    if (lane == 0) red[w] = v;
    __syncthreads();
    float t = red[0];
    #pragma unroll
    for (int i = 1; i < 8; i++) t += red[i];
    return t;
}

__global__ void __launch_bounds__(256)
ln_kernel(const float* __restrict__ in, const float* __restrict__ gam,
          const float* __restrict__ bet,
          __nv_bfloat16* __restrict__ outh, __nv_bfloat16* __restrict__ outl)
{
    __shared__ float red[8];
    int r = blockIdx.x, tid = threadIdx.x;
    float v = in[r * Dd + tid];
    float mean = blocksum256(v, red) * (1.f / Dd);
    float dv = v - mean;
    float var = blocksum256(dv * dv, red) * (1.f / Dd);
    float o = dv * rsqrtf(var + 1e-5f) * gam[tid] + bet[tid];
    __nv_bfloat16 h, l; split_bf16(o, h, l);
    outh[r * Dd + tid] = h;
    outl[r * Dd + tid] = l;
}

// ---------------- pool + heads ----------------
__global__ void __launch_bounds__(256)
pool_kernel(const float* __restrict__ x, float* __restrict__ s)
{
    int b = blockIdx.x, d = threadIdx.x;
    float acc = 0.f;
    #pragma unroll 8
    for (int i = 0; i < Kk; i++) acc += x[(b * Kk + i) * Dd + d];
    s[b * Dd + d] = acc;
}

__global__ void __launch_bounds__(LSs)
head_kernel(const float* __restrict__ s,
            const float* __restrict__ pw, const float* __restrict__ pb,
            const float* __restrict__ muw, const float* __restrict__ mub,
            const float* __restrict__ spw, const float* __restrict__ spb,
            float* __restrict__ out)
{
    int b = blockIdx.x, n = threadIdx.x;
    __shared__ float ss[Dd];
    __shared__ float sh[LSs];
    ss[n]       = s[b * Dd + n];
    ss[n + 128] = s[b * Dd + n + 128];
    __syncthreads();

    float acc = pb[n];
    #pragma unroll 8
    for (int d = 0; d < Dd; d++) acc = fmaf(ss[d], pw[n * Dd + d], acc);
    sh[n] = 0.5f * acc * (1.0f + erff(acc * 0.7071067811865476f));
    __syncthreads();

    float mu = mub[n], sc = spb[n];
    #pragma unroll 8
    for (int d = 0; d < LSs; d++) {
        mu = fmaf(sh[d], muw[n * LSs + d], mu);
        sc = fmaf(sh[d], spw[n * LSs + d], sc);
    }
    float spv = fmaxf(sc, 0.f) + log1pf(expf(-fabsf(sc)));
    out[b * LSs + n] = mu;
    out[Bb * LSs + b * LSs + n] = spv;
}

// ---------------- launch ----------------
extern "C" void kernel_launch(void* const* d_in, const int* in_sizes, int n_in,
                              void* d_out, int out_size)
{
    (void)in_sizes; (void)n_in; (void)out_size;
    const float* X    = (const float*)d_in[0];
    const float* k_w  = (const float*)d_in[1];
    const float* q_w  = (const float*)d_in[2];
    const float* rw1  = (const float*)d_in[3];
    const float* rb1  = (const float*)d_in[4];
    const float* rw2  = (const float*)d_in[5];
    const float* rb2  = (const float*)d_in[6];
    const float* lng  = (const float*)d_in[7];
    const float* lnb  = (const float*)d_in[8];
    const float* mw1  = (const float*)d_in[9];
    const float* mb1  = (const float*)d_in[10];
    const float* mw2  = (const float*)d_in[11];
    const float* mb2  = (const float*)d_in[12];
    const float* pw   = (const float*)d_in[13];
    const float* pb   = (const float*)d_in[14];
    const float* muw  = (const float*)d_in[15];
    const float* mub  = (const float*)d_in[16];
    const float* spw  = (const float*)d_in[17];
    const float* spb  = (const float*)d_in[18];
    float* out = (float*)d_out;

    static float *px=nullptr,*pqkab=nullptr,*php=nullptr,*pbc=nullptr,*ps=nullptr;
    static __nv_bfloat16 *pxh,*pxl,*pggh,*pggl,*phh,*phl,*pth,*ptl,*pwch,*pwcl,*pw2h,*pw2l;
    if (!px) {
        cudaGetSymbolAddress((void**)&px,    g_x);
        cudaGetSymbolAddress((void**)&pqkab, g_qkab);
        cudaGetSymbolAddress((void**)&php,   g_hp);
        cudaGetSymbolAddress((void**)&pbc,   g_bc);
        cudaGetSymbolAddress((void**)&ps,    g_s);
        cudaGetSymbolAddress((void**)&pxh,   g_xh);
        cudaGetSymbolAddress((void**)&pxl,   g_xl);
        cudaGetSymbolAddress((void**)&pggh,  g_ggh);
        cudaGetSymbolAddress((void**)&pggl,  g_ggl);
        cudaGetSymbolAddress((void**)&phh,   g_hh);
        cudaGetSymbolAddress((void**)&phl,   g_hl);
        cudaGetSymbolAddress((void**)&pth,   g_th);
        cudaGetSymbolAddress((void**)&ptl,   g_tl);
        cudaGetSymbolAddress((void**)&pwch,  g_wch);
        cudaGetSymbolAddress((void**)&pwcl,  g_wcl);
        cudaGetSymbolAddress((void**)&pw2h,  g_w2h);
        cudaGetSymbolAddress((void**)&pw2l,  g_w2l);
        cudaFuncSetAttribute(tc_gemm, cudaFuncAttributeMaxDynamicSharedMemorySize, SM_TOT);
    }

    copy_conv_kernel<<<(Mm * Dd) / 256, 256>>>(X, px, pxh, pxl, Mm * Dd);

    for (int l = 0; l < NLl; l++) {
        const float* rw1_l = rw1 + l * Dd * 2 * Dd;
        const float* rb1_l = rb1 + l * Dd;
        const float* rw2_l = rw2 + l * Dd * Dd;
        const float* rb2_l = rb2 + l * Dd;
        const float* lg_l  = lng + l * Dd;
        const float* lb_l  = lnb + l * Dd;
        const float* mw1_l = mw1 + l * Dd * Dd;
        const float* mb1_l = mb1 + l * Dd;
        const float* mw2_l = mw2 + l * Dd * Dd;
        const float* mb2_l = mb2 + l * Dd;

        pack_kernel<<<(4 * Dd * Dd) / 256, 256>>>(k_w + l * Dd * Dd, q_w + l * Dd * Dd,
                                                  rw1_l, rb1_l, pwch, pwcl, pbc);
        w2pack_kernel<<<(3 * Dd * Dd) / 256, 256>>>(rw2_l, mw1_l, mw2_l, pw2h, pw2l);

        // fused k|q|a|bb projection: [2048,256] @ [1024,256]^T -> qkab fp32
        tc_gemm<<<dim3(16, 16), 256, SM_TOT>>>(pxh, pxl, pwch, pwcl, pbc, nullptr,
                                               pqkab, QS, nullptr, nullptr, 0);

        attn_kernel<<<dim3(Kk / 4, Bb), 256>>>(pqkab, pggh, pggl);

        // agg proj + residual -> php (fp32)
        tc_gemm<<<dim3(4, 16), 256, SM_TOT>>>(pggh, pggl, pw2h, pw2l, rb2_l, px,
                                              php, Dd, nullptr, nullptr, 0);
        ln_kernel<<<Mm, 256>>>(php, lg_l, lb_l, phh, phl);
        // mlp1 (gelu) -> t duals only
        tc_gemm<<<dim3(4, 16), 256, SM_TOT>>>(phh, phl, pw2h + Dd * Dd, pw2l + Dd * Dd,
                                              mb1_l, nullptr, nullptr, Dd, pth, ptl, 1);
        // mlp2 + residual -> px fp32 + duals
        tc_gemm<<<dim3(4, 16), 256, SM_TOT>>>(pth, ptl, pw2h + 2 * Dd * Dd, pw2l + 2 * Dd * Dd,
                                              mb2_l, px, px, Dd, pxh, pxl, 0);
    }

    pool_kernel<<<Bb, 256>>>(px, ps);
    head_kernel<<<Bb, LSs>>>(ps, pw, pb, muw, mub, spw, spb, out);
}

// round 7
// speedup vs baseline: 1.0011x; 1.0011x over previous
#include <cuda_runtime.h>
#include <cuda_bf16.h>
#include <math.h>
#include <cstdint>

#define Bb   32
#define Kk   64
#define Dd   256
#define LSs  128
#define NLl  2
#define Mm   (Bb*Kk)          // 2048 rows
#define QS   1024             // qkab row stride
#define GK   256              // GEMM K

// ---------------- scratch (no allocs allowed) ----------------
__device__ float g_x   [Mm*Dd];
__device__ float g_qkab[Mm*QS];
__device__ float g_hp  [Mm*Dd];
__device__ float g_bc  [4*Dd];
__device__ float g_s   [Bb*Dd];
// bf16 hi/lo duals
__device__ __nv_bfloat16 g_xh [Mm*Dd], g_xl [Mm*Dd];
__device__ __nv_bfloat16 g_ggh[Mm*Dd], g_ggl[Mm*Dd];
__device__ __nv_bfloat16 g_hh [Mm*Dd], g_hl [Mm*Dd];
__device__ __nv_bfloat16 g_th [Mm*Dd], g_tl [Mm*Dd];
__device__ __nv_bfloat16 g_wch[4*Dd*Dd], g_wcl[4*Dd*Dd];
__device__ __nv_bfloat16 g_w2h[3*Dd*Dd], g_w2l[3*Dd*Dd];

// ---------------- fast exact-enough gelu (A&S 7.1.26, |err| < 2e-7) ----------------
__device__ __forceinline__ float gelu_fast(float x) {
    float z = fabsf(x) * 0.7071067811865476f;
    float w = fmaf(z, 0.3275911f, 1.0f);
    float t;
    asm("rcp.approx.f32 %0, %1;" : "=f"(t) : "f"(w));
    float ez = __expf(-z * z);
    float p = fmaf(fmaf(fmaf(fmaf(1.061405429f, t, -1.453152027f), t,
                     1.421413741f), t, -0.284496736f), t, 0.254829592f) * t;
    float e = fmaf(-p, ez, 1.0f);                 // erf(|z|)
    float phi = fmaf(copysignf(e, x), 0.5f, 0.5f);
    return x * phi;
}

__device__ __forceinline__ uint32_t smem_u32(const void* p) {
    uint32_t a;
    asm("{ .reg .u64 t; cvta.to.shared.u64 t, %1; cvt.u32.u64 %0, t; }" : "=r"(a) : "l"(p));
    return a;
}

// split fp32 -> (hi, lo) bf16
__device__ __forceinline__ void split_bf16(float v, __nv_bfloat16& h, __nv_bfloat16& l) {
    h = __float2bfloat16(v);
    l = __float2bfloat16(v - __bfloat162float(h));
}
// pack pair (x0, x1) -> bf16x2 words for hi and lo
__device__ __forceinline__ void split_pair(float x0, float x1, uint32_t& hp, uint32_t& lp) {
    asm("cvt.rn.bf16x2.f32 %0, %1, %2;" : "=r"(hp) : "f"(x1), "f"(x0));
    float h0 = __uint_as_float(hp << 16);
    float h1 = __uint_as_float(hp & 0xffff0000u);
    asm("cvt.rn.bf16x2.f32 %0, %1, %2;" : "=r"(lp) : "f"(x1 - h1), "f"(x0 - h0));
}

// ---------------- warp MMA primitives ----------------
__device__ __forceinline__ void ldsm_x4(uint32_t* r, uint32_t addr) {
    asm volatile("ldmatrix.sync.aligned.m8n8.x4.shared.b16 {%0,%1,%2,%3}, [%4];"
        : "=r"(r[0]), "=r"(r[1]), "=r"(r[2]), "=r"(r[3]) : "r"(addr));
}
__device__ __forceinline__ void ldsm_x2(uint32_t* r, uint32_t addr) {
    asm volatile("ldmatrix.sync.aligned.m8n8.x2.shared.b16 {%0,%1}, [%2];"
        : "=r"(r[0]), "=r"(r[1]) : "r"(addr));
}
__device__ __forceinline__ void mma_bf16(float* c, const uint32_t* a, const uint32_t* b) {
    asm volatile("mma.sync.aligned.m16n8k16.row.col.f32.bf16.bf16.f32 "
        "{%0,%1,%2,%3}, {%4,%5,%6,%7}, {%8,%9}, {%0,%1,%2,%3};"
        : "+f"(c[0]), "+f"(c[1]), "+f"(c[2]), "+f"(c[3])
        : "r"(a[0]), "r"(a[1]), "r"(a[2]), "r"(a[3]), "r"(b[0]), "r"(b[1]));
}

// ---------------- smem layout for tc_gemm ----------------
#define LDSB  528
#define SM_AH 0
#define SM_AL (SM_AH + 128*LDSB)
#define SM_BH (SM_AL + 128*LDSB)
#define SM_BL (SM_BH + 64*LDSB)
#define SM_TOT (SM_BL + 64*LDSB)     // 202752 B

// stage pre-converted bf16 duals: pure uint4 copies
template<int ROWS>
__device__ __forceinline__ void stage_dual(const __nv_bfloat16* __restrict__ Gh,
                                           const __nv_bfloat16* __restrict__ Gl,
                                           char* smh, char* sml, int tid) {
    const int ngroups = ROWS * (GK / 8);
    for (int g = tid; g < ngroups; g += 256) {
        int row = g >> 5;
        int k0  = (g & 31) * 8;
        uint4 vh = *(const uint4*)(Gh + (size_t)row * GK + k0);
        uint4 vl = *(const uint4*)(Gl + (size_t)row * GK + k0);
        uint32_t off = (uint32_t)(row * LDSB + k0 * 2);
        *(uint4*)(smh + off) = vh;
        *(uint4*)(sml + off) = vl;
    }
}

// ---------------- bf16x3 GEMM: C = A[M,256] @ Bw[N,256]^T (+bias)(+gelu)(+resid) ----
// CTA: 128x64 tile, 8 warps (4M x 2N), warp tile 32x32.
// Cf (fp32, stride ldc) optional; Ch/Cl (bf16 duals, stride 256) optional.
__global__ void __launch_bounds__(256)
tc_gemm(const __nv_bfloat16* __restrict__ Ah, const __nv_bfloat16* __restrict__ Al,
        const __nv_bfloat16* __restrict__ Bh, const __nv_bfloat16* __restrict__ Bl,
        const float* __restrict__ bias, const float* __restrict__ resid,
        float* __restrict__ Cf, int ldc,
        __nv_bfloat16* __restrict__ Ch, __nv_bfloat16* __restrict__ Cl,
        int do_gelu)
{
    extern __shared__ char sm[];
    uint32_t smb = smem_u32(sm);
    const int tid = threadIdx.x, lane = tid & 31, wid = tid >> 5;
    const int warp_m = wid & 3, warp_n = wid >> 2;
    const int bm = blockIdx.y * 128, bn = blockIdx.x * 64;

    stage_dual<128>(Ah + (size_t)bm * GK, Al + (size_t)bm * GK, sm + SM_AH, sm + SM_AL, tid);
    stage_dual<64>( Bh + (size_t)bn * GK, Bl + (size_t)bn * GK, sm + SM_BH, sm + SM_BL, tid);
    __syncthreads();

    float acc[2][4][4];
    #pragma unroll
    for (int i = 0; i < 2; i++)
        #pragma unroll
        for (int j = 0; j < 4; j++)
            #pragma unroll
            for (int e = 0; e < 4; e++) acc[i][j][e] = 0.f;

    uint32_t a_base[2], b_base[4];
    #pragma unroll
    for (int tm = 0; tm < 2; tm++)
        a_base[tm] = smb + SM_AH
                   + (uint32_t)((warp_m * 32 + tm * 16 + (lane & 15)) * LDSB)
                   + (uint32_t)((lane >> 4) * 16);
    #pragma unroll
    for (int tn = 0; tn < 4; tn++)
        b_base[tn] = smb + SM_BH
                   + (uint32_t)((warp_n * 32 + tn * 8 + (lane & 7)) * LDSB)
                   + (uint32_t)(((lane >> 3) & 1) * 16);

    const uint32_t DA = SM_AL - SM_AH;
    const uint32_t DB = SM_BL - SM_BH;

    #pragma unroll
    for (int ks = 0; ks < 16; ks++) {
        const uint32_t kb = ks * 32;
        uint32_t ah[2][4], al[2][4], bh[4][2], bl[4][2];
        #pragma unroll
        for (int tm = 0; tm < 2; tm++) {
            ldsm_x4(ah[tm], a_base[tm] + kb);
            ldsm_x4(al[tm], a_base[tm] + kb + DA);
        }
        #pragma unroll
        for (int tn = 0; tn < 4; tn++) {
            ldsm_x2(bh[tn], b_base[tn] + kb);
            ldsm_x2(bl[tn], b_base[tn] + kb + DB);
        }
        #pragma unroll
        for (int tm = 0; tm < 2; tm++)
            #pragma unroll
            for (int tn = 0; tn < 4; tn++) {
                mma_bf16(acc[tm][tn], ah[tm], bh[tn]);
                mma_bf16(acc[tm][tn], ah[tm], bl[tn]);
                mma_bf16(acc[tm][tn], al[tm], bh[tn]);
            }
    }

    #pragma unroll
    for (int tm = 0; tm < 2; tm++) {
        int r0 = bm + warp_m * 32 + tm * 16 + (lane >> 2);
        #pragma unroll
        for (int tn = 0; tn < 4; tn++) {
            int c = bn + warp_n * 32 + tn * 8 + (lane & 3) * 2;
            #pragma unroll
            for (int h = 0; h < 2; h++) {
                int r = r0 + h * 8;
                float x0 = acc[tm][tn][h * 2 + 0];
                float x1 = acc[tm][tn][h * 2 + 1];
                if (bias)  { x0 += bias[c]; x1 += bias[c + 1]; }
                if (do_gelu) { x0 = gelu_fast(x0); x1 = gelu_fast(x1); }
                if (resid) {
                    float2 rr = *(const float2*)(resid + (size_t)r * ldc + c);
                    x0 += rr.x; x1 += rr.y;
                }
                if (Cf) *(float2*)(Cf + (size_t)r * ldc + c) = make_float2(x0, x1);
                if (Ch) {
                    uint32_t hp, lp;
                    split_pair(x0, x1, hp, lp);
                    *(uint32_t*)(Ch + (size_t)r * Dd + c) = hp;
                    *(uint32_t*)(Cl + (size_t)r * Dd + c) = lp;
                }
            }
        }
    }
}

// ---------------- producer/conversion kernels ----------------
__global__ void copy_conv_kernel(const float* __restrict__ src, float* __restrict__ dst,
                                 __nv_bfloat16* __restrict__ dh, __nv_bfloat16* __restrict__ dl,
                                 int n) {
    int i = blockIdx.x * blockDim.x + threadIdx.x;
    if (i < n) {
        float v = src[i];
        dst[i] = v;
        __nv_bfloat16 h, l; split_bf16(v, h, l);
        dh[i] = h; dl[i] = l;
    }
}

// pack combined weights (duals): rows [0:256)=k_w, [256:512)=q_w, [512:768)=W1a+W1b, [768:1024)=W1b
__global__ void pack_kernel(const float* __restrict__ kw, const float* __restrict__ qw,
                            const float* __restrict__ w1, const float* __restrict__ rb1,
                            __nv_bfloat16* __restrict__ wch, __nv_bfloat16* __restrict__ wcl,
                            float* __restrict__ bc) {
    int i = blockIdx.x * blockDim.x + threadIdx.x;
    int r = i >> 8, c = i & 255;
    float v;
    if (r < 256)      v = kw[r * Dd + c];
    else if (r < 512) v = qw[(r - 256) * Dd + c];
    else if (r < 768) { int d = r - 512; v = w1[d * 2 * Dd + c] + w1[d * 2 * Dd + Dd + c]; }
    else              { int d = r - 768; v = w1[d * 2 * Dd + Dd + c]; }
    __nv_bfloat16 h, l; split_bf16(v, h, l);
    wch[i] = h; wcl[i] = l;
    if (i < 4 * Dd) bc[i] = (i >= 512 && i < 768) ? rb1[i - 512] : 0.f;
}

// pack rw2|mw1|mw2 as dual slabs
__global__ void w2pack_kernel(const float* __restrict__ rw2, const float* __restrict__ mw1,
                              const float* __restrict__ mw2,
                              __nv_bfloat16* __restrict__ w2h, __nv_bfloat16* __restrict__ w2l) {
    int i = blockIdx.x * blockDim.x + threadIdx.x;   // [0, 3*65536)
    int s = i >> 16, o = i & 65535;
    const float* src = (s == 0) ? rw2 : ((s == 1) ? mw1 : mw2);
    float v = src[o];
    __nv_bfloat16 h, l; split_bf16(v, h, l);
    w2h[i] = h; w2l[i] = l;
}

// ---------------- attention + gelu aggregation, 4 queries per block ----------------
// qkab row layout: [k(256) | q(256) | a(256) | bb(256)]
__global__ void __launch_bounds__(256)
attn_kernel(const float* __restrict__ qkab,
            __nv_bfloat16* __restrict__ ggh, __nv_bfloat16* __restrict__ ggl)
{
    const int b = blockIdx.y, i0 = blockIdx.x * 4;
    const int tid = threadIdx.x;
    const int lane = tid & 31, warp = tid >> 5;

    __shared__ float sq[4][Dd];
    __shared__ float sa[4][Dd];
    __shared__ float sl[4][Kk];
    __shared__ float sp[4][Kk];

    const float* base = qkab + (size_t)b * Kk * QS;

    #pragma unroll
    for (int ii = 0; ii < 4; ii++) {
        const float* row = base + (size_t)(i0 + ii) * QS;
        sq[ii][tid] = row[256 + tid];
        sa[ii][tid] = row[512 + tid];
    }
    __syncthreads();

    // logits: warp handles j, computes dots for all 4 queries (k loaded once)
    for (int j = warp; j < Kk; j += 8) {
        const float* kj = base + (size_t)j * QS;
        float kv[8];
        #pragma unroll
        for (int m = 0; m < 8; m++) kv[m] = kj[lane + 32 * m];
        #pragma unroll
        for (int ii = 0; ii < 4; ii++) {
            float t = 0.f;
            #pragma unroll
            for (int m = 0; m < 8; m++) t = fmaf(sq[ii][lane + 32 * m], kv[m], t);
            #pragma unroll
            for (int o = 16; o; o >>= 1) t += __shfl_xor_sync(0xffffffffu, t, o);
            if (lane == 0) sl[ii][j] = t * 0.0625f;   // D^-0.5
        }
    }
    __syncthreads();

    // 4 softmaxes: warp w < 4 handles query w
    if (warp < 4) {
        float v0 = sl[warp][lane], v1 = sl[warp][lane + 32];
        float m = fmaxf(v0, v1);
        #pragma unroll
        for (int o = 16; o; o >>= 1) m = fmaxf(m, __shfl_xor_sync(0xffffffffu, m, o));
        float e0 = __expf(v0 - m), e1 = __expf(v1 - m);
        float s = e0 + e1;
        #pragma unroll
        for (int o = 16; o; o >>= 1) s += __shfl_xor_sync(0xffffffffu, s, o);
        float inv = 1.f / s;
        sp[warp][lane] = e0 * inv; sp[warp][lane + 32] = e1 * inv;
    }
    __syncthreads();

    // aggregation: thread owns dim d = tid; bb loaded once, 4 gelu per j
    const float a0 = sa[0][tid], a1 = sa[1][tid], a2 = sa[2][tid], a3 = sa[3][tid];
    float c0 = 0.f, c1 = 0.f, c2 = 0.f, c3 = 0.f;
    const float* bbp = base + 768 + tid;
    #pragma unroll 4
    for (int j = 0; j < Kk; j++) {
        float bb = __ldg(bbp + (size_t)j * QS);
        c0 = fmaf(sp[0][j], gelu_fast(a0 - bb), c0);
        c1 = fmaf(sp[1][j], gelu_fast(a1 - bb), c1);
        c2 = fmaf(sp[2][j], gelu_fast(a2 - bb), c2);
        c3 = fmaf(sp[3][j], gelu_fast(a3 - bb), c3);
    }
    float cc[4] = {c0, c1, c2, c3};
    #pragma unroll
    for (int ii = 0; ii < 4; ii++) {
        size_t idx = (size_t)(b * Kk + i0 + ii) * Dd + tid;
        __nv_bfloat16 h, l; split_bf16(cc[ii], h, l);
        ggh[idx] = h; ggl[idx] = l;
    }
}

// ---------------- layernorm over D=256 -> duals only ----------------
__device__ __forceinline__ float blocksum256(float v, float* red) {
    int lane = threadIdx.x & 31, w = threadIdx.x >> 5;
    #pragma unroll
    for (int o = 16; o; o >>= 1) v += __shfl_xor_sync(0xffffffffu, v, o);
    __syncthreads();
    if (lane == 0) red[w] = v;
    __syncthreads();
    float t = red[0];
    #pragma unroll
    for (int i = 1; i < 8; i++) t += red[i];
    return t;
}

__global__ void __launch_bounds__(256)
ln_kernel(const float* __restrict__ in, const float* __restrict__ gam,
          const float* __restrict__ bet,
          __nv_bfloat16* __restrict__ outh, __nv_bfloat16* __restrict__ outl)
{
    __shared__ float red[8];
    int r = blockIdx.x, tid = threadIdx.x;
    float v = in[r * Dd + tid];
    float mean = blocksum256(v, red) * (1.f / Dd);
    float dv = v - mean;
    float var = blocksum256(dv * dv, red) * (1.f / Dd);
    float o = dv * rsqrtf(var + 1e-5f) * gam[tid] + bet[tid];
    __nv_bfloat16 h, l; split_bf16(o, h, l);
    outh[r * Dd + tid] = h;
    outl[r * Dd + tid] = l;
}

// ---------------- pool + heads ----------------
__global__ void __launch_bounds__(256)
pool_kernel(const float* __restrict__ x, float* __restrict__ s)
{
    int b = blockIdx.x, d = threadIdx.x;
    float acc = 0.f;
    #pragma unroll 8
    for (int i = 0; i < Kk; i++) acc += x[(b * Kk + i) * Dd + d];
    s[b * Dd + d] = acc;
}

__global__ void __launch_bounds__(LSs)
head_kernel(const float* __restrict__ s,
            const float* __restrict__ pw, const float* __restrict__ pb,
            const float* __restrict__ muw, const float* __restrict__ mub,
            const float* __restrict__ spw, const float* __restrict__ spb,
            float* __restrict__ out)
{
    int b = blockIdx.x, n = threadIdx.x;
    __shared__ float ss[Dd];
    __shared__ float sh[LSs];
    ss[n]       = s[b * Dd + n];
    ss[n + 128] = s[b * Dd + n + 128];
    __syncthreads();

    float acc = pb[n];
    #pragma unroll 8
    for (int d = 0; d < Dd; d++) acc = fmaf(ss[d], pw[n * Dd + d], acc);
    sh[n] = 0.5f * acc * (1.0f + erff(acc * 0.7071067811865476f));
    __syncthreads();

    float mu = mub[n], sc = spb[n];
    #pragma unroll 8
    for (int d = 0; d < LSs; d++) {
        mu = fmaf(sh[d], muw[n * LSs + d], mu);
        sc = fmaf(sh[d], spw[n * LSs + d], sc);
    }
    float spv = fmaxf(sc, 0.f) + log1pf(expf(-fabsf(sc)));
    out[b * LSs + n] = mu;
    out[Bb * LSs + b * LSs + n] = spv;
}

// ---------------- launch ----------------
extern "C" void kernel_launch(void* const* d_in, const int* in_sizes, int n_in,
                              void* d_out, int out_size)
{
    (void)in_sizes; (void)n_in; (void)out_size;
    const float* X    = (const float*)d_in[0];
    const float* k_w  = (const float*)d_in[1];
    const float* q_w  = (const float*)d_in[2];
    const float* rw1  = (const float*)d_in[3];
    const float* rb1  = (const float*)d_in[4];
    const float* rw2  = (const float*)d_in[5];
    const float* rb2  = (const float*)d_in[6];
    const float* lng  = (const float*)d_in[7];
    const float* lnb  = (const float*)d_in[8];
    const float* mw1  = (const float*)d_in[9];
    const float* mb1  = (const float*)d_in[10];
    const float* mw2  = (const float*)d_in[11];
    const float* mb2  = (const float*)d_in[12];
    const float* pw   = (const float*)d_in[13];
    const float* pb   = (const float*)d_in[14];
    const float* muw  = (const float*)d_in[15];
    const float* mub  = (const float*)d_in[16];
    const float* spw  = (const float*)d_in[17];
    const float* spb  = (const float*)d_in[18];
    float* out = (float*)d_out;

    static float *px=nullptr,*pqkab=nullptr,*php=nullptr,*pbc=nullptr,*ps=nullptr;
    static __nv_bfloat16 *pxh,*pxl,*pggh,*pggl,*phh,*phl,*pth,*ptl,*pwch,*pwcl,*pw2h,*pw2l;
    if (!px) {
        cudaGetSymbolAddress((void**)&px,    g_x);
        cudaGetSymbolAddress((void**)&pqkab, g_qkab);
        cudaGetSymbolAddress((void**)&php,   g_hp);
        cudaGetSymbolAddress((void**)&pbc,   g_bc);
        cudaGetSymbolAddress((void**)&ps,    g_s);
        cudaGetSymbolAddress((void**)&pxh,   g_xh);
        cudaGetSymbolAddress((void**)&pxl,   g_xl);
        cudaGetSymbolAddress((void**)&pggh,  g_ggh);
        cudaGetSymbolAddress((void**)&pggl,  g_ggl);
        cudaGetSymbolAddress((void**)&phh,   g_hh);
        cudaGetSymbolAddress((void**)&phl,   g_hl);
        cudaGetSymbolAddress((void**)&pth,   g_th);
        cudaGetSymbolAddress((void**)&ptl,   g_tl);
        cudaGetSymbolAddress((void**)&pwch,  g_wch);
        cudaGetSymbolAddress((void**)&pwcl,  g_wcl);
        cudaGetSymbolAddress((void**)&pw2h,  g_w2h);
        cudaGetSymbolAddress((void**)&pw2l,  g_w2l);
        cudaFuncSetAttribute(tc_gemm, cudaFuncAttributeMaxDynamicSharedMemorySize, SM_TOT);
    }

    copy_conv_kernel<<<(Mm * Dd) / 256, 256>>>(X, px, pxh, pxl, Mm * Dd);

    for (int l = 0; l < NLl; l++) {
        const float* rw1_l = rw1 + l * Dd * 2 * Dd;
        const float* rb1_l = rb1 + l * Dd;
        const float* rw2_l = rw2 + l * Dd * Dd;
        const float* rb2_l = rb2 + l * Dd;
        const float* lg_l  = lng + l * Dd;
        const float* lb_l  = lnb + l * Dd;
        const float* mw1_l = mw1 + l * Dd * Dd;
        const float* mb1_l = mb1 + l * Dd;
        const float* mw2_l = mw2 + l * Dd * Dd;
        const float* mb2_l = mb2 + l * Dd;

        pack_kernel<<<(4 * Dd * Dd) / 256, 256>>>(k_w + l * Dd * Dd, q_w + l * Dd * Dd,
                                                  rw1_l, rb1_l, pwch, pwcl, pbc);
        w2pack_kernel<<<(3 * Dd * Dd) / 256, 256>>>(rw2_l, mw1_l, mw2_l, pw2h, pw2l);

        // fused k|q|a|bb projection: [2048,256] @ [1024,256]^T -> qkab fp32
        tc_gemm<<<dim3(16, 16), 256, SM_TOT>>>(pxh, pxl, pwch, pwcl, pbc, nullptr,
                                               pqkab, QS, nullptr, nullptr, 0);

        attn_kernel<<<dim3(Kk / 4, Bb), 256>>>(pqkab, pggh, pggl);

        // agg proj + residual -> php (fp32)
        tc_gemm<<<dim3(4, 16), 256, SM_TOT>>>(pggh, pggl, pw2h, pw2l, rb2_l, px,
                                              php, Dd, nullptr, nullptr, 0);
        ln_kernel<<<Mm, 256>>>(php, lg_l, lb_l, phh, phl);
        // mlp1 (gelu) -> t duals only
        tc_gemm<<<dim3(4, 16), 256, SM_TOT>>>(phh, phl, pw2h + Dd * Dd, pw2l + Dd * Dd,
                                              mb1_l, nullptr, nullptr, Dd, pth, ptl, 1);
        // mlp2 + residual -> px fp32 + duals
        tc_gemm<<<dim3(4, 16), 256, SM_TOT>>>(pth, ptl, pw2h + 2 * Dd * Dd, pw2l + 2 * Dd * Dd,
                                              mb2_l, px, px, Dd, pxh, pxl, 0);
    }

    pool_kernel<<<Bb, 256>>>(px, ps);
    head_kernel<<<Bb, LSs>>>(ps, pw, pb, muw, mub, spw, spb, out);
}

// round 8
// speedup vs baseline: 1.1110x; 1.1098x over previous
#include <cuda_runtime.h>
#include <cuda_bf16.h>
#include <math.h>
#include <cstdint>

#define Bb   32
#define Kk   64
#define Dd   256
#define LSs  128
#define NLl  2
#define Mm   (Bb*Kk)          // 2048 rows
#define QS   1024             // qkab row stride
#define GK   256              // GEMM K

// ---------------- scratch (no allocs allowed) ----------------
__device__ float g_x   [Mm*Dd];
__device__ float g_qkab[Mm*QS];
__device__ float g_hp  [Mm*Dd];
__device__ float g_bc  [4*Dd];
__device__ float g_s   [Bb*Dd];
// bf16 hi/lo duals
__device__ __nv_bfloat16 g_xh [Mm*Dd], g_xl [Mm*Dd];
__device__ __nv_bfloat16 g_ggh[Mm*Dd], g_ggl[Mm*Dd];
__device__ __nv_bfloat16 g_hh [Mm*Dd], g_hl [Mm*Dd];
__device__ __nv_bfloat16 g_th [Mm*Dd], g_tl [Mm*Dd];
__device__ __nv_bfloat16 g_wch[4*Dd*Dd], g_wcl[4*Dd*Dd];
__device__ __nv_bfloat16 g_w2h[3*Dd*Dd], g_w2l[3*Dd*Dd];

// ---------------- fast exact-enough gelu (A&S 7.1.26, |err| < 2e-7) ----------------
__device__ __forceinline__ float gelu_fast(float x) {
    float z = fabsf(x) * 0.7071067811865476f;
    float w = fmaf(z, 0.3275911f, 1.0f);
    float t;
    asm("rcp.approx.f32 %0, %1;" : "=f"(t) : "f"(w));
    float ez = __expf(-z * z);
    float p = fmaf(fmaf(fmaf(fmaf(1.061405429f, t, -1.453152027f), t,
                     1.421413741f), t, -0.284496736f), t, 0.254829592f) * t;
    float e = fmaf(-p, ez, 1.0f);                 // erf(|z|)
    float phi = fmaf(copysignf(e, x), 0.5f, 0.5f);
    return x * phi;
}

__device__ __forceinline__ uint32_t smem_u32(const void* p) {
    uint32_t a;
    asm("{ .reg .u64 t; cvta.to.shared.u64 t, %1; cvt.u32.u64 %0, t; }" : "=r"(a) : "l"(p));
    return a;
}

__device__ __forceinline__ void split_bf16(float v, __nv_bfloat16& h, __nv_bfloat16& l) {
    h = __float2bfloat16(v);
    l = __float2bfloat16(v - __bfloat162float(h));
}
__device__ __forceinline__ void split_pair(float x0, float x1, uint32_t& hp, uint32_t& lp) {
    asm("cvt.rn.bf16x2.f32 %0, %1, %2;" : "=r"(hp) : "f"(x1), "f"(x0));
    float h0 = __uint_as_float(hp << 16);
    float h1 = __uint_as_float(hp & 0xffff0000u);
    asm("cvt.rn.bf16x2.f32 %0, %1, %2;" : "=r"(lp) : "f"(x1 - h1), "f"(x0 - h0));
}

// ---------------- warp MMA primitives ----------------
__device__ __forceinline__ void ldsm_x4(uint32_t* r, uint32_t addr) {
    asm volatile("ldmatrix.sync.aligned.m8n8.x4.shared.b16 {%0,%1,%2,%3}, [%4];"
        : "=r"(r[0]), "=r"(r[1]), "=r"(r[2]), "=r"(r[3]) : "r"(addr));
}
__device__ __forceinline__ void ldsm_x2(uint32_t* r, uint32_t addr) {
    asm volatile("ldmatrix.sync.aligned.m8n8.x2.shared.b16 {%0,%1}, [%2];"
        : "=r"(r[0]), "=r"(r[1]) : "r"(addr));
}
__device__ __forceinline__ void mma_bf16(float* c, const uint32_t* a, const uint32_t* b) {
    asm volatile("mma.sync.aligned.m16n8k16.row.col.f32.bf16.bf16.f32 "
        "{%0,%1,%2,%3}, {%4,%5,%6,%7}, {%8,%9}, {%0,%1,%2,%3};"
        : "+f"(c[0]), "+f"(c[1]), "+f"(c[2]), "+f"(c[3])
        : "r"(a[0]), "r"(a[1]), "r"(a[2]), "r"(a[3]), "r"(b[0]), "r"(b[1]));
}

// ---------------- smem layout ----------------
#define LDSB  528

// stage pre-converted bf16 duals: pure uint4 copies
template<int ROWS>
__device__ __forceinline__ void stage_dual(const __nv_bfloat16* __restrict__ Gh,
                                           const __nv_bfloat16* __restrict__ Gl,
                                           char* smh, char* sml, int tid) {
    const int ngroups = ROWS * (GK / 8);
    for (int g = tid; g < ngroups; g += 256) {
        int row = g >> 5;
        int k0  = (g & 31) * 8;
        uint4 vh = *(const uint4*)(Gh + (size_t)row * GK + k0);
        uint4 vl = *(const uint4*)(Gl + (size_t)row * GK + k0);
        uint32_t off = (uint32_t)(row * LDSB + k0 * 2);
        *(uint4*)(smh + off) = vh;
        *(uint4*)(sml + off) = vl;
    }
}

template<int TN>
__device__ __forceinline__ void load_frags(uint32_t kb,
        uint32_t (&ah)[2][4], uint32_t (&al)[2][4],
        uint32_t (&bh)[TN][2], uint32_t (&bl)[TN][2],
        const uint32_t* a_base, const uint32_t* b_base,
        uint32_t DA, uint32_t DB) {
    #pragma unroll
    for (int tm = 0; tm < 2; tm++) {
        ldsm_x4(ah[tm], a_base[tm] + kb);
        ldsm_x4(al[tm], a_base[tm] + kb + DA);
    }
    #pragma unroll
    for (int tn = 0; tn < TN; tn++) {
        ldsm_x2(bh[tn], b_base[tn] + kb);
        ldsm_x2(bl[tn], b_base[tn] + kb + DB);
    }
}

// ---------------- bf16x3 GEMM: C = A[M,256] @ Bw[N,256]^T (+bias)(+gelu)(+resid) ----
// CTA: 128 x (NT*NTILES) output; A staged once, B staged per n-tile stage.
// 8 warps: 4 m-rows x 2 n-cols; warp tile 32 x NT/2 (TN = NT/16 n8-tiles).
template<int NT, int NTILES>
__global__ void __launch_bounds__(256)
tc_gemm(const __nv_bfloat16* __restrict__ Ah, const __nv_bfloat16* __restrict__ Al,
        const __nv_bfloat16* __restrict__ Bh, const __nv_bfloat16* __restrict__ Bl,
        const float* __restrict__ bias, const float* __restrict__ resid,
        float* __restrict__ Cf, int ldc,
        __nv_bfloat16* __restrict__ Ch, __nv_bfloat16* __restrict__ Cl,
        int do_gelu)
{
    constexpr int TN = NT / 16;
    constexpr int SM_AH = 0;
    constexpr int SM_AL = 128 * LDSB;
    constexpr int SM_BH = 2 * 128 * LDSB;
    constexpr int SM_BL = SM_BH + NT * LDSB;

    extern __shared__ char sm[];
    uint32_t smb = smem_u32(sm);
    const int tid = threadIdx.x, lane = tid & 31, wid = tid >> 5;
    const int warp_m = wid & 3, warp_n = wid >> 2;
    const int bm = blockIdx.y * 128, bn0 = blockIdx.x * (NT * NTILES);

    stage_dual<128>(Ah + (size_t)bm * GK, Al + (size_t)bm * GK, sm + SM_AH, sm + SM_AL, tid);

    uint32_t a_base[2], b_base[TN];
    #pragma unroll
    for (int tm = 0; tm < 2; tm++)
        a_base[tm] = smb + SM_AH
                   + (uint32_t)((warp_m * 32 + tm * 16 + (lane & 15)) * LDSB)
                   + (uint32_t)((lane >> 4) * 16);
    #pragma unroll
    for (int tn = 0; tn < TN; tn++)
        b_base[tn] = smb + SM_BH
                   + (uint32_t)((warp_n * (NT / 2) + tn * 8 + (lane & 7)) * LDSB)
                   + (uint32_t)(((lane >> 3) & 1) * 16);

    const uint32_t DA = SM_AL - SM_AH;
    const uint32_t DB = SM_BL - SM_BH;

    #pragma unroll 1
    for (int t = 0; t < NTILES; t++) {
        const int bn = bn0 + t * NT;
        stage_dual<NT>(Bh + (size_t)bn * GK, Bl + (size_t)bn * GK,
                       sm + SM_BH, sm + SM_BL, tid);
        __syncthreads();

        float acc[2][TN][4];
        #pragma unroll
        for (int i = 0; i < 2; i++)
            #pragma unroll
            for (int j = 0; j < TN; j++)
                #pragma unroll
                for (int e = 0; e < 4; e++) acc[i][j][e] = 0.f;

        // register double-buffered fragments, product-major MMA order
        uint32_t ah[2][2][4], al[2][2][4], bh[2][TN][2], bl[2][TN][2];
        load_frags<TN>(0, ah[0], al[0], bh[0], bl[0], a_base, b_base, DA, DB);

        #pragma unroll
        for (int ks = 0; ks < 16; ks++) {
            const int cur = ks & 1, nxt = cur ^ 1;
            if (ks < 15)
                load_frags<TN>((uint32_t)((ks + 1) * 32),
                               ah[nxt], al[nxt], bh[nxt], bl[nxt],
                               a_base, b_base, DA, DB);
            #pragma unroll
            for (int tm = 0; tm < 2; tm++)
                #pragma unroll
                for (int tn = 0; tn < TN; tn++)
                    mma_bf16(acc[tm][tn], ah[cur][tm], bh[cur][tn]);
            #pragma unroll
            for (int tm = 0; tm < 2; tm++)
                #pragma unroll
                for (int tn = 0; tn < TN; tn++)
                    mma_bf16(acc[tm][tn], ah[cur][tm], bl[cur][tn]);
            #pragma unroll
            for (int tm = 0; tm < 2; tm++)
                #pragma unroll
                for (int tn = 0; tn < TN; tn++)
                    mma_bf16(acc[tm][tn], al[cur][tm], bh[cur][tn]);
        }

        // epilogue
        #pragma unroll
        for (int tm = 0; tm < 2; tm++) {
            int r0 = bm + warp_m * 32 + tm * 16 + (lane >> 2);
            #pragma unroll
            for (int tn = 0; tn < TN; tn++) {
                int c = bn + warp_n * (NT / 2) + tn * 8 + (lane & 3) * 2;
                #pragma unroll
                for (int h = 0; h < 2; h++) {
                    int r = r0 + h * 8;
                    float x0 = acc[tm][tn][h * 2 + 0];
                    float x1 = acc[tm][tn][h * 2 + 1];
                    if (bias)  { x0 += bias[c]; x1 += bias[c + 1]; }
                    if (do_gelu) { x0 = gelu_fast(x0); x1 = gelu_fast(x1); }
                    if (resid) {
                        float2 rr = *(const float2*)(resid + (size_t)r * ldc + c);
                        x0 += rr.x; x1 += rr.y;
                    }
                    if (Cf) *(float2*)(Cf + (size_t)r * ldc + c) = make_float2(x0, x1);
                    if (Ch) {
                        uint32_t hp, lp;
                        split_pair(x0, x1, hp, lp);
                        *(uint32_t*)(Ch + (size_t)r * Dd + c) = hp;
                        *(uint32_t*)(Cl + (size_t)r * Dd + c) = lp;
                    }
                }
            }
        }
        if (t + 1 < NTILES) __syncthreads();   // protect B smem before restage
    }
}

#define SM_TOT_BIG   ((2*128 + 2*64) * LDSB)   // 202752
#define SM_TOT_SMALL ((2*128 + 2*32) * LDSB)   // 168960

// ---------------- producer/conversion kernels ----------------
__global__ void copy_conv_kernel(const float* __restrict__ src, float* __restrict__ dst,
                                 __nv_bfloat16* __restrict__ dh, __nv_bfloat16* __restrict__ dl,
                                 int n) {
    int i = blockIdx.x * blockDim.x + threadIdx.x;
    if (i < n) {
        float v = src[i];
        dst[i] = v;
        __nv_bfloat16 h, l; split_bf16(v, h, l);
        dh[i] = h; dl[i] = l;
    }
}

// pack combined weights (duals): rows [0:256)=k_w, [256:512)=q_w, [512:768)=W1a+W1b, [768:1024)=W1b
__global__ void pack_kernel(const float* __restrict__ kw, const float* __restrict__ qw,
                            const float* __restrict__ w1, const float* __restrict__ rb1,
                            __nv_bfloat16* __restrict__ wch, __nv_bfloat16* __restrict__ wcl,
                            float* __restrict__ bc) {
    int i = blockIdx.x * blockDim.x + threadIdx.x;
    int r = i >> 8, c = i & 255;
    float v;
    if (r < 256)      v = kw[r * Dd + c];
    else if (r < 512) v = qw[(r - 256) * Dd + c];
    else if (r < 768) { int d = r - 512; v = w1[d * 2 * Dd + c] + w1[d * 2 * Dd + Dd + c]; }
    else              { int d = r - 768; v = w1[d * 2 * Dd + Dd + c]; }
    __nv_bfloat16 h, l; split_bf16(v, h, l);
    wch[i] = h; wcl[i] = l;
    if (i < 4 * Dd) bc[i] = (i >= 512 && i < 768) ? rb1[i - 512] : 0.f;
}

// pack rw2|mw1|mw2 as dual slabs
__global__ void w2pack_kernel(const float* __restrict__ rw2, const float* __restrict__ mw1,
                              const float* __restrict__ mw2,
                              __nv_bfloat16* __restrict__ w2h, __nv_bfloat16* __restrict__ w2l) {
    int i = blockIdx.x * blockDim.x + threadIdx.x;   // [0, 3*65536)
    int s = i >> 16, o = i & 65535;
    const float* src = (s == 0) ? rw2 : ((s == 1) ? mw1 : mw2);
    float v = src[o];
    __nv_bfloat16 h, l; split_bf16(v, h, l);
    w2h[i] = h; w2l[i] = l;
}

// ---------------- attention + gelu aggregation, 4 queries per block ----------------
// qkab row layout: [k(256) | q(256) | a(256) | bb(256)]
__global__ void __launch_bounds__(256)
attn_kernel(const float* __restrict__ qkab,
            __nv_bfloat16* __restrict__ ggh, __nv_bfloat16* __restrict__ ggl)
{
    const int b = blockIdx.y, i0 = blockIdx.x * 4;
    const int tid = threadIdx.x;
    const int lane = tid & 31, warp = tid >> 5;

    __shared__ float sq[4][Dd];
    __shared__ float sa[4][Dd];
    __shared__ float sl[4][Kk];
    __shared__ float sp[4][Kk];

    const float* base = qkab + (size_t)b * Kk * QS;

    #pragma unroll
    for (int ii = 0; ii < 4; ii++) {
        const float* row = base + (size_t)(i0 + ii) * QS;
        sq[ii][tid] = row[256 + tid];
        sa[ii][tid] = row[512 + tid];
    }
    __syncthreads();

    for (int j = warp; j < Kk; j += 8) {
        const float* kj = base + (size_t)j * QS;
        float kv[8];
        #pragma unroll
        for (int m = 0; m < 8; m++) kv[m] = kj[lane + 32 * m];
        #pragma unroll
        for (int ii = 0; ii < 4; ii++) {
            float t = 0.f;
            #pragma unroll
            for (int m = 0; m < 8; m++) t = fmaf(sq[ii][lane + 32 * m], kv[m], t);
            #pragma unroll
            for (int o = 16; o; o >>= 1) t += __shfl_xor_sync(0xffffffffu, t, o);
            if (lane == 0) sl[ii][j] = t * 0.0625f;   // D^-0.5
        }
    }
    __syncthreads();

    if (warp < 4) {
        float v0 = sl[warp][lane], v1 = sl[warp][lane + 32];
        float m = fmaxf(v0, v1);
        #pragma unroll
        for (int o = 16; o; o >>= 1) m = fmaxf(m, __shfl_xor_sync(0xffffffffu, m, o));
        float e0 = __expf(v0 - m), e1 = __expf(v1 - m);
        float s = e0 + e1;
        #pragma unroll
        for (int o = 16; o; o >>= 1) s += __shfl_xor_sync(0xffffffffu, s, o);
        float inv = 1.f / s;
        sp[warp][lane] = e0 * inv; sp[warp][lane + 32] = e1 * inv;
    }
    __syncthreads();

    const float a0 = sa[0][tid], a1 = sa[1][tid], a2 = sa[2][tid], a3 = sa[3][tid];
    float c0 = 0.f, c1 = 0.f, c2 = 0.f, c3 = 0.f;
    const float* bbp = base + 768 + tid;
    #pragma unroll 4
    for (int j = 0; j < Kk; j++) {
        float bb = __ldg(bbp + (size_t)j * QS);
        c0 = fmaf(sp[0][j], gelu_fast(a0 - bb), c0);
        c1 = fmaf(sp[1][j], gelu_fast(a1 - bb), c1);
        c2 = fmaf(sp[2][j], gelu_fast(a2 - bb), c2);
        c3 = fmaf(sp[3][j], gelu_fast(a3 - bb), c3);
    }
    float cc[4] = {c0, c1, c2, c3};
    #pragma unroll
    for (int ii = 0; ii < 4; ii++) {
        size_t idx = (size_t)(b * Kk + i0 + ii) * Dd + tid;
        __nv_bfloat16 h, l; split_bf16(cc[ii], h, l);
        ggh[idx] = h; ggl[idx] = l;
    }
}

// ---------------- layernorm over D=256 -> duals only ----------------
__device__ __forceinline__ float blocksum256(float v, float* red) {
    int lane = threadIdx.x & 31, w = threadIdx.x >> 5;
    #pragma unroll
    for (int o = 16; o; o >>= 1) v += __shfl_xor_sync(0xffffffffu, v, o);
    __syncthreads();
    if (lane == 0) red[w] = v;
    __syncthreads();
    float t = red[0];
    #pragma unroll
    for (int i = 1; i < 8; i++) t += red[i];
    return t;
}

__global__ void __launch_bounds__(256)
ln_kernel(const float* __restrict__ in, const float* __restrict__ gam,
          const float* __restrict__ bet,
          __nv_bfloat16* __restrict__ outh, __nv_bfloat16* __restrict__ outl)
{
    __shared__ float red[8];
    int r = blockIdx.x, tid = threadIdx.x;
    float v = in[r * Dd + tid];
    float mean = blocksum256(v, red) * (1.f / Dd);
    float dv = v - mean;
    float var = blocksum256(dv * dv, red) * (1.f / Dd);
    float o = dv * rsqrtf(var + 1e-5f) * gam[tid] + bet[tid];
    __nv_bfloat16 h, l; split_bf16(o, h, l);
    outh[r * Dd + tid] = h;
    outl[r * Dd + tid] = l;
}

// ---------------- pool + heads ----------------
__global__ void __launch_bounds__(256)
pool_kernel(const float* __restrict__ x, float* __restrict__ s)
{
    int b = blockIdx.x, d = threadIdx.x;
    float acc = 0.f;
    #pragma unroll 8
    for (int i = 0; i < Kk; i++) acc += x[(b * Kk + i) * Dd + d];
    s[b * Dd + d] = acc;
}

__global__ void __launch_bounds__(LSs)
head_kernel(const float* __restrict__ s,
            const float* __restrict__ pw, const float* __restrict__ pb,
            const float* __restrict__ muw, const float* __restrict__ mub,
            const float* __restrict__ spw, const float* __restrict__ spb,
            float* __restrict__ out)
{
    int b = blockIdx.x, n = threadIdx.x;
    __shared__ float ss[Dd];
    __shared__ float sh[LSs];
    ss[n]       = s[b * Dd + n];
    ss[n + 128] = s[b * Dd + n + 128];
    __syncthreads();

    float acc = pb[n];
    #pragma unroll 8
    for (int d = 0; d < Dd; d++) acc = fmaf(ss[d], pw[n * Dd + d], acc);
    sh[n] = 0.5f * acc * (1.0f + erff(acc * 0.7071067811865476f));
    __syncthreads();

    float mu = mub[n], sc = spb[n];
    #pragma unroll 8
    for (int d = 0; d < LSs; d++) {
        mu = fmaf(sh[d], muw[n * LSs + d], mu);
        sc = fmaf(sh[d], spw[n * LSs + d], sc);
    }
    float spv = fmaxf(sc, 0.f) + log1pf(expf(-fabsf(sc)));
    out[b * LSs + n] = mu;
    out[Bb * LSs + b * LSs + n] = spv;
}

// ---------------- launch ----------------
extern "C" void kernel_launch(void* const* d_in, const int* in_sizes, int n_in,
                              void* d_out, int out_size)
{
    (void)in_sizes; (void)n_in; (void)out_size;
    const float* X    = (const float*)d_in[0];
    const float* k_w  = (const float*)d_in[1];
    const float* q_w  = (const float*)d_in[2];
    const float* rw1  = (const float*)d_in[3];
    const float* rb1  = (const float*)d_in[4];
    const float* rw2  = (const float*)d_in[5];
    const float* rb2  = (const float*)d_in[6];
    const float* lng  = (const float*)d_in[7];
    const float* lnb  = (const float*)d_in[8];
    const float* mw1  = (const float*)d_in[9];
    const float* mb1  = (const float*)d_in[10];
    const float* mw2  = (const float*)d_in[11];
    const float* mb2  = (const float*)d_in[12];
    const float* pw   = (const float*)d_in[13];
    const float* pb   = (const float*)d_in[14];
    const float* muw  = (const float*)d_in[15];
    const float* mub  = (const float*)d_in[16];
    const float* spw  = (const float*)d_in[17];
    const float* spb  = (const float*)d_in[18];
    float* out = (float*)d_out;

    static float *px=nullptr,*pqkab=nullptr,*php=nullptr,*pbc=nullptr,*ps=nullptr;
    static __nv_bfloat16 *pxh,*pxl,*pggh,*pggl,*phh,*phl,*pth,*ptl,*pwch,*pwcl,*pw2h,*pw2l;
    if (!px) {
        cudaGetSymbolAddress((void**)&px,    g_x);
        cudaGetSymbolAddress((void**)&pqkab, g_qkab);
        cudaGetSymbolAddress((void**)&php,   g_hp);
        cudaGetSymbolAddress((void**)&pbc,   g_bc);
        cudaGetSymbolAddress((void**)&ps,    g_s);
        cudaGetSymbolAddress((void**)&pxh,   g_xh);
        cudaGetSymbolAddress((void**)&pxl,   g_xl);
        cudaGetSymbolAddress((void**)&pggh,  g_ggh);
        cudaGetSymbolAddress((void**)&pggl,  g_ggl);
        cudaGetSymbolAddress((void**)&phh,   g_hh);
        cudaGetSymbolAddress((void**)&phl,   g_hl);
        cudaGetSymbolAddress((void**)&pth,   g_th);
        cudaGetSymbolAddress((void**)&ptl,   g_tl);
        cudaGetSymbolAddress((void**)&pwch,  g_wch);
        cudaGetSymbolAddress((void**)&pwcl,  g_wcl);
        cudaGetSymbolAddress((void**)&pw2h,  g_w2h);
        cudaGetSymbolAddress((void**)&pw2l,  g_w2l);
        cudaFuncSetAttribute(tc_gemm<64, 2>, cudaFuncAttributeMaxDynamicSharedMemorySize, SM_TOT_BIG);
        cudaFuncSetAttribute(tc_gemm<32, 1>, cudaFuncAttributeMaxDynamicSharedMemorySize, SM_TOT_SMALL);
    }

    copy_conv_kernel<<<(Mm * Dd) / 256, 256>>>(X, px, pxh, pxl, Mm * Dd);

    for (int l = 0; l < NLl; l++) {
        const float* rw1_l = rw1 + l * Dd * 2 * Dd;
        const float* rb1_l = rb1 + l * Dd;
        const float* rw2_l = rw2 + l * Dd * Dd;
        const float* rb2_l = rb2 + l * Dd;
        const float* lg_l  = lng + l * Dd;
        const float* lb_l  = lnb + l * Dd;
        const float* mw1_l = mw1 + l * Dd * Dd;
        const float* mb1_l = mb1 + l * Dd;
        const float* mw2_l = mw2 + l * Dd * Dd;
        const float* mb2_l = mb2 + l * Dd;

        pack_kernel<<<(4 * Dd * Dd) / 256, 256>>>(k_w + l * Dd * Dd, q_w + l * Dd * Dd,
                                                  rw1_l, rb1_l, pwch, pwcl, pbc);
        w2pack_kernel<<<(3 * Dd * Dd) / 256, 256>>>(rw2_l, mw1_l, mw2_l, pw2h, pw2l);

        // fused k|q|a|bb projection: [2048,256] @ [1024,256]^T -> qkab fp32 (1 wave: 128 CTAs)
        tc_gemm<64, 2><<<dim3(8, 16), 256, SM_TOT_BIG>>>(
            pxh, pxl, pwch, pwcl, pbc, nullptr, pqkab, QS, nullptr, nullptr, 0);

        attn_kernel<<<dim3(Kk / 4, Bb), 256>>>(pqkab, pggh, pggl);

        // agg proj + residual -> php (fp32)   (128 CTAs)
        tc_gemm<32, 1><<<dim3(8, 16), 256, SM_TOT_SMALL>>>(
            pggh, pggl, pw2h, pw2l, rb2_l, px, php, Dd, nullptr, nullptr, 0);
        ln_kernel<<<Mm, 256>>>(php, lg_l, lb_l, phh, phl);
        // mlp1 (gelu) -> t duals only
        tc_gemm<32, 1><<<dim3(8, 16), 256, SM_TOT_SMALL>>>(
            phh, phl, pw2h + Dd * Dd, pw2l + Dd * Dd, mb1_l, nullptr, nullptr, Dd, pth, ptl, 1);
        // mlp2 + residual -> px fp32 + duals
        tc_gemm<32, 1><<<dim3(8, 16), 256, SM_TOT_SMALL>>>(
            pth, ptl, pw2h + 2 * Dd * Dd, pw2l + 2 * Dd * Dd, mb2_l, px, px, Dd, pxh, pxl, 0);
    }

    pool_kernel<<<Bb, 256>>>(px, ps);
    head_kernel<<<Bb, LSs>>>(ps, pw, pb, muw, mub, spw, spb, out);
}

// round 12
// speedup vs baseline: 1.2177x; 1.0960x over previous
#include <cuda_runtime.h>
#include <cuda_bf16.h>
#include <math.h>
#include <cstdint>

#define Bb   32
#define Kk   64
#define Dd   256
#define LSs  128
#define NLl  2
#define Mm   (Bb*Kk)          // 2048 rows
#define QS   1024             // qkab row stride
#define GK   256              // GEMM K
#define KC   128              // K chunk
#define LDSC 272              // smem row stride bytes for 128 bf16 cols (+16 pad)

// ---------------- scratch (no allocs allowed) ----------------
__device__ float g_x   [Mm*Dd];
__device__ float g_qkab[Mm*QS];
__device__ float g_hp  [Mm*Dd];
__device__ float g_bc  [4*Dd];
__device__ float g_s   [Bb*Dd];
// bf16 hi/lo duals
__device__ __nv_bfloat16 g_xh [Mm*Dd], g_xl [Mm*Dd];
__device__ __nv_bfloat16 g_ggh[Mm*Dd], g_ggl[Mm*Dd];
__device__ __nv_bfloat16 g_hh [Mm*Dd], g_hl [Mm*Dd];
__device__ __nv_bfloat16 g_th [Mm*Dd], g_tl [Mm*Dd];
__device__ __nv_bfloat16 g_wch[4*Dd*Dd], g_wcl[4*Dd*Dd];
__device__ __nv_bfloat16 g_w2h[3*Dd*Dd], g_w2l[3*Dd*Dd];

// ---------------- fast exact-enough gelu (A&S 7.1.26, |err| < 2e-7) ----------------
__device__ __forceinline__ float gelu_fast(float x) {
    float z = fabsf(x) * 0.7071067811865476f;
    float w = fmaf(z, 0.3275911f, 1.0f);
    float t;
    asm("rcp.approx.f32 %0, %1;" : "=f"(t) : "f"(w));
    float ez = __expf(-z * z);
    float p = fmaf(fmaf(fmaf(fmaf(1.061405429f, t, -1.453152027f), t,
                     1.421413741f), t, -0.284496736f), t, 0.254829592f) * t;
    float e = fmaf(-p, ez, 1.0f);                 // erf(|z|)
    float phi = fmaf(copysignf(e, x), 0.5f, 0.5f);
    return x * phi;
}

__device__ __forceinline__ uint32_t smem_u32(const void* p) {
    uint32_t a;
    asm("{ .reg .u64 t; cvta.to.shared.u64 t, %1; cvt.u32.u64 %0, t; }" : "=r"(a) : "l"(p));
    return a;
}

__device__ __forceinline__ void split_bf16(float v, __nv_bfloat16& h, __nv_bfloat16& l) {
    h = __float2bfloat16(v);
    l = __float2bfloat16(v - __bfloat162float(h));
}
__device__ __forceinline__ void split_pair(float x0, float x1, uint32_t& hp, uint32_t& lp) {
    asm("cvt.rn.bf16x2.f32 %0, %1, %2;" : "=r"(hp) : "f"(x1), "f"(x0));
    float h0 = __uint_as_float(hp << 16);
    float h1 = __uint_as_float(hp & 0xffff0000u);
    asm("cvt.rn.bf16x2.f32 %0, %1, %2;" : "=r"(lp) : "f"(x1 - h1), "f"(x0 - h0));
}

// ---------------- warp MMA primitives ----------------
__device__ __forceinline__ void ldsm_x4(uint32_t* r, uint32_t addr) {
    asm volatile("ldmatrix.sync.aligned.m8n8.x4.shared.b16 {%0,%1,%2,%3}, [%4];"
        : "=r"(r[0]), "=r"(r[1]), "=r"(r[2]), "=r"(r[3]) : "r"(addr));
}
__device__ __forceinline__ void ldsm_x2(uint32_t* r, uint32_t addr) {
    asm volatile("ldmatrix.sync.aligned.m8n8.x2.shared.b16 {%0,%1}, [%2];"
        : "=r"(r[0]), "=r"(r[1]) : "r"(addr));
}
__device__ __forceinline__ void mma_bf16(float* c, const uint32_t* a, const uint32_t* b) {
    asm volatile("mma.sync.aligned.m16n8k16.row.col.f32.bf16.bf16.f32 "
        "{%0,%1,%2,%3}, {%4,%5,%6,%7}, {%8,%9}, {%0,%1,%2,%3};"
        : "+f"(c[0]), "+f"(c[1]), "+f"(c[2]), "+f"(c[3])
        : "r"(a[0]), "r"(a[1]), "r"(a[2]), "r"(a[3]), "r"(b[0]), "r"(b[1]));
}

// stage a KC-wide chunk of a dual tile: pure uint4 copies
template<int ROWS, int THREADS>
__device__ __forceinline__ void stage_chunk(const __nv_bfloat16* __restrict__ Gh,
                                            const __nv_bfloat16* __restrict__ Gl,
                                            char* smh, char* sml, int tid) {
    const int ngroups = ROWS * (KC / 8);
    #pragma unroll
    for (int g = tid; g < ngroups; g += THREADS) {
        int row = g >> 4;
        int k0  = (g & 15) * 8;
        uint4 vh = *(const uint4*)(Gh + (size_t)row * GK + k0);
        uint4 vl = *(const uint4*)(Gl + (size_t)row * GK + k0);
        uint32_t off = (uint32_t)(row * LDSC + k0 * 2);
        *(uint4*)(smh + off) = vh;
        *(uint4*)(sml + off) = vl;
    }
}

template<int TM, int TN>
__device__ __forceinline__ void load_frags(uint32_t kb,
        uint32_t (&ah)[TM][4], uint32_t (&al)[TM][4],
        uint32_t (&bh)[TN][2], uint32_t (&bl)[TN][2],
        const uint32_t* a_base, const uint32_t* b_base,
        uint32_t DA, uint32_t DB) {
    #pragma unroll
    for (int tm = 0; tm < TM; tm++) {
        ldsm_x4(ah[tm], a_base[tm] + kb);
        ldsm_x4(al[tm], a_base[tm] + kb + DA);
    }
    #pragma unroll
    for (int tn = 0; tn < TN; tn++) {
        ldsm_x2(bh[tn], b_base[tn] + kb);
        ldsm_x2(bl[tn], b_base[tn] + kb + DB);
    }
}

// ---------------- bf16x3 GEMM: C = A[M,256] @ Bw[N,256]^T (+bias)(+gelu)(+resid) ----
// CTA: BM x BN tile; K chunked (2 x 128) so smem fits multiple CTAs/SM.
// Warp grid: (BM/WM) x (BN/WN); warp tile WM x WN; TM=WM/16, TN=WN/8.
template<int BM, int BN, int WM, int WN>
__global__ void __launch_bounds__((BM/WM)*(BN/WN)*32)
tc_gemm(const __nv_bfloat16* __restrict__ Ah, const __nv_bfloat16* __restrict__ Al,
        const __nv_bfloat16* __restrict__ Bh, const __nv_bfloat16* __restrict__ Bl,
        const float* __restrict__ bias, const float* __restrict__ resid,
        float* __restrict__ Cf, int ldc,
        __nv_bfloat16* __restrict__ Ch, __nv_bfloat16* __restrict__ Cl,
        int do_gelu)
{
    constexpr int TM = WM / 16, TN = WN / 8;
    constexpr int WARPS_N = BN / WN;
    constexpr int THREADS = (BM / WM) * (BN / WN) * 32;
    constexpr int SM_AH = 0;
    constexpr int SM_AL = BM * LDSC;
    constexpr int SM_BH = 2 * BM * LDSC;
    constexpr int SM_BL = SM_BH + BN * LDSC;

    extern __shared__ char sm[];
    uint32_t smb = smem_u32(sm);
    const int tid = threadIdx.x, lane = tid & 31, wid = tid >> 5;
    const int warp_m = wid / WARPS_N, warp_n = wid % WARPS_N;
    const int bm = blockIdx.y * BM, bn = blockIdx.x * BN;

    uint32_t a_base[TM], b_base[TN];
    #pragma unroll
    for (int tm = 0; tm < TM; tm++)
        a_base[tm] = smb + SM_AH
                   + (uint32_t)((warp_m * WM + tm * 16 + (lane & 15)) * LDSC)
                   + (uint32_t)((lane >> 4) * 16);
    #pragma unroll
    for (int tn = 0; tn < TN; tn++)
        b_base[tn] = smb + SM_BH
                   + (uint32_t)((warp_n * WN + tn * 8 + (lane & 7)) * LDSC)
                   + (uint32_t)(((lane >> 3) & 1) * 16);

    const uint32_t DA = SM_AL - SM_AH;
    const uint32_t DB = SM_BL - SM_BH;

    float acc[TM][TN][4];
    #pragma unroll
    for (int i = 0; i < TM; i++)
        #pragma unroll
        for (int j = 0; j < TN; j++)
            #pragma unroll
            for (int e = 0; e < 4; e++) acc[i][j][e] = 0.f;

    uint32_t ah[2][TM][4], al[2][TM][4], bh[2][TN][2], bl[2][TN][2];

    #pragma unroll 1
    for (int kc = 0; kc < GK / KC; kc++) {
        if (kc) __syncthreads();   // protect smem before restage
        stage_chunk<BM, THREADS>(Ah + (size_t)bm * GK + kc * KC,
                                 Al + (size_t)bm * GK + kc * KC,
                                 sm + SM_AH, sm + SM_AL, tid);
        stage_chunk<BN, THREADS>(Bh + (size_t)bn * GK + kc * KC,
                                 Bl + (size_t)bn * GK + kc * KC,
                                 sm + SM_BH, sm + SM_BL, tid);
        __syncthreads();

        load_frags<TM, TN>(0, ah[0], al[0], bh[0], bl[0], a_base, b_base, DA, DB);

        #pragma unroll
        for (int ks = 0; ks < KC / 16; ks++) {
            const int cur = ks & 1, nxt = cur ^ 1;
            if (ks < KC / 16 - 1)
                load_frags<TM, TN>((uint32_t)((ks + 1) * 32),
                                   ah[nxt], al[nxt], bh[nxt], bl[nxt],
                                   a_base, b_base, DA, DB);
            #pragma unroll
            for (int tm = 0; tm < TM; tm++)
                #pragma unroll
                for (int tn = 0; tn < TN; tn++)
                    mma_bf16(acc[tm][tn], ah[cur][tm], bh[cur][tn]);
            #pragma unroll
            for (int tm = 0; tm < TM; tm++)
                #pragma unroll
                for (int tn = 0; tn < TN; tn++)
                    mma_bf16(acc[tm][tn], ah[cur][tm], bl[cur][tn]);
            #pragma unroll
            for (int tm = 0; tm < TM; tm++)
                #pragma unroll
                for (int tn = 0; tn < TN; tn++)
                    mma_bf16(acc[tm][tn], al[cur][tm], bh[cur][tn]);
        }
    }

    // epilogue
    #pragma unroll
    for (int tm = 0; tm < TM; tm++) {
        int r0 = bm + warp_m * WM + tm * 16 + (lane >> 2);
        #pragma unroll
        for (int tn = 0; tn < TN; tn++) {
            int c = bn + warp_n * WN + tn * 8 + (lane & 3) * 2;
            #pragma unroll
            for (int h = 0; h < 2; h++) {
                int r = r0 + h * 8;
                float x0 = acc[tm][tn][h * 2 + 0];
                float x1 = acc[tm][tn][h * 2 + 1];
                if (bias)  { x0 += bias[c]; x1 += bias[c + 1]; }
                if (do_gelu) { x0 = gelu_fast(x0); x1 = gelu_fast(x1); }
                if (resid) {
                    float2 rr = *(const float2*)(resid + (size_t)r * ldc + c);
                    x0 += rr.x; x1 += rr.y;
                }
                if (Cf) *(float2*)(Cf + (size_t)r * ldc + c) = make_float2(x0, x1);
                if (Ch) {
                    uint32_t hp, lp;
                    split_pair(x0, x1, hp, lp);
                    *(uint32_t*)(Ch + (size_t)r * Dd + c) = hp;
                    *(uint32_t*)(Cl + (size_t)r * Dd + c) = lp;
                }
            }
        }
    }
}

// smem sizes
#define SM_BIG   (2 * (128 + 64) * LDSC)   // 104448 -> 2 CTAs/SM
#define SM_SMALL (2 * (64 + 32) * LDSC)    // 52224  -> 4 CTAs/SM

// ---------------- producer/conversion kernels ----------------
__global__ void copy_conv_kernel(const float* __restrict__ src, float* __restrict__ dst,
                                 __nv_bfloat16* __restrict__ dh, __nv_bfloat16* __restrict__ dl,
                                 int n) {
    int i = blockIdx.x * blockDim.x + threadIdx.x;
    if (i < n) {
        float v = src[i];
        dst[i] = v;
        __nv_bfloat16 h, l; split_bf16(v, h, l);
        dh[i] = h; dl[i] = l;
    }
}

// pack combined weights (duals): rows [0:256)=k_w, [256:512)=q_w, [512:768)=W1a+W1b, [768:1024)=W1b
__global__ void pack_kernel(const float* __restrict__ kw, const float* __restrict__ qw,
                            const float* __restrict__ w1, const float* __restrict__ rb1,
                            __nv_bfloat16* __restrict__ wch, __nv_bfloat16* __restrict__ wcl,
                            float* __restrict__ bc) {
    int i = blockIdx.x * blockDim.x + threadIdx.x;
    int r = i >> 8, c = i & 255;
    float v;
    if (r < 256)      v = kw[r * Dd + c];
    else if (r < 512) v = qw[(r - 256) * Dd + c];
    else if (r < 768) { int d = r - 512; v = w1[d * 2 * Dd + c] + w1[d * 2 * Dd + Dd + c]; }
    else              { int d = r - 768; v = w1[d * 2 * Dd + Dd + c]; }
    __nv_bfloat16 h, l; split_bf16(v, h, l);
    wch[i] = h; wcl[i] = l;
    if (i < 4 * Dd) bc[i] = (i >= 512 && i < 768) ? rb1[i - 512] : 0.f;
}

// pack rw2|mw1|mw2 as dual slabs
__global__ void w2pack_kernel(const float* __restrict__ rw2, const float* __restrict__ mw1,
                              const float* __restrict__ mw2,
                              __nv_bfloat16* __restrict__ w2h, __nv_bfloat16* __restrict__ w2l) {
    int i = blockIdx.x * blockDim.x + threadIdx.x;   // [0, 3*65536)
    int s = i >> 16, o = i & 65535;
    const float* src = (s == 0) ? rw2 : ((s == 1) ? mw1 : mw2);
    float v = src[o];
    __nv_bfloat16 h, l; split_bf16(v, h, l);
    w2h[i] = h; w2l[i] = l;
}

// ---------------- attention + gelu aggregation, 4 queries per block ----------------
// qkab row layout: [k(256) | q(256) | a(256) | bb(256)]
__global__ void __launch_bounds__(256)
attn_kernel(const float* __restrict__ qkab,
            __nv_bfloat16* __restrict__ ggh, __nv_bfloat16* __restrict__ ggl)
{
    const int b = blockIdx.y, i0 = blockIdx.x * 4;
    const int tid = threadIdx.x;
    const int lane = tid & 31, warp = tid >> 5;

    __shared__ float sq[4][Dd];
    __shared__ float sa[4][Dd];
    __shared__ float sl[4][Kk];
    __shared__ float sp[4][Kk];

    const float* base = qkab + (size_t)b * Kk * QS;

    #pragma unroll
    for (int ii = 0; ii < 4; ii++) {
        const float* row = base + (size_t)(i0 + ii) * QS;
        sq[ii][tid] = row[256 + tid];
        sa[ii][tid] = row[512 + tid];
    }
    __syncthreads();

    for (int j = warp; j < Kk; j += 8) {
        const float* kj = base + (size_t)j * QS;
        float kv[8];
        #pragma unroll
        for (int m = 0; m < 8; m++) kv[m] = kj[lane + 32 * m];
        #pragma unroll
        for (int ii = 0; ii < 4; ii++) {
            float t = 0.f;
            #pragma unroll
            for (int m = 0; m < 8; m++) t = fmaf(sq[ii][lane + 32 * m], kv[m], t);
            #pragma unroll
            for (int o = 16; o; o >>= 1) t += __shfl_xor_sync(0xffffffffu, t, o);
            if (lane == 0) sl[ii][j] = t * 0.0625f;   // D^-0.5
        }
    }
    __syncthreads();

    if (warp < 4) {
        float v0 = sl[warp][lane], v1 = sl[warp][lane + 32];
        float m = fmaxf(v0, v1);
        #pragma unroll
        for (int o = 16; o; o >>= 1) m = fmaxf(m, __shfl_xor_sync(0xffffffffu, m, o));
        float e0 = __expf(v0 - m), e1 = __expf(v1 - m);
        float s = e0 + e1;
        #pragma unroll
        for (int o = 16; o; o >>= 1) s += __shfl_xor_sync(0xffffffffu, s, o);
        float inv = 1.f / s;
        sp[warp][lane] = e0 * inv; sp[warp][lane + 32] = e1 * inv;
    }
    __syncthreads();

    const float a0 = sa[0][tid], a1 = sa[1][tid], a2 = sa[2][tid], a3 = sa[3][tid];
    float c0 = 0.f, c1 = 0.f, c2 = 0.f, c3 = 0.f;
    const float* bbp = base + 768 + tid;
    #pragma unroll 4
    for (int j = 0; j < Kk; j++) {
        float bb = __ldg(bbp + (size_t)j * QS);
        c0 = fmaf(sp[0][j], gelu_fast(a0 - bb), c0);
        c1 = fmaf(sp[1][j], gelu_fast(a1 - bb), c1);
        c2 = fmaf(sp[2][j], gelu_fast(a2 - bb), c2);
        c3 = fmaf(sp[3][j], gelu_fast(a3 - bb), c3);
    }
    float cc[4] = {c0, c1, c2, c3};
    #pragma unroll
    for (int ii = 0; ii < 4; ii++) {
        size_t idx = (size_t)(b * Kk + i0 + ii) * Dd + tid;
        __nv_bfloat16 h, l; split_bf16(cc[ii], h, l);
        ggh[idx] = h; ggl[idx] = l;
    }
}

// ---------------- layernorm over D=256 -> duals only ----------------
__device__ __forceinline__ float blocksum256(float v, float* red) {
    int lane = threadIdx.x & 31, w = threadIdx.x >> 5;
    #pragma unroll
    for (int o = 16; o; o >>= 1) v += __shfl_xor_sync(0xffffffffu, v, o);
    __syncthreads();
    if (lane == 0) red[w] = v;
    __syncthreads();
    float t = red[0];
    #pragma unroll
    for (int i = 1; i < 8; i++) t += red[i];
    return t;
}

__global__ void __launch_bounds__(256)
ln_kernel(const float* __restrict__ in, const float* __restrict__ gam,
          const float* __restrict__ bet,
          __nv_bfloat16* __restrict__ outh, __nv_bfloat16* __restrict__ outl)
{
    __shared__ float red[8];
    int r = blockIdx.x, tid = threadIdx.x;
    float v = in[r * Dd + tid];
    float mean = blocksum256(v, red) * (1.f / Dd);
    float dv = v - mean;
    float var = blocksum256(dv * dv, red) * (1.f / Dd);
    float o = dv * rsqrtf(var + 1e-5f) * gam[tid] + bet[tid];
    __nv_bfloat16 h, l; split_bf16(o, h, l);
    outh[r * Dd + tid] = h;
    outl[r * Dd + tid] = l;
}

// ---------------- pool + heads ----------------
__global__ void __launch_bounds__(256)
pool_kernel(const float* __restrict__ x, float* __restrict__ s)
{
    int b = blockIdx.x, d = threadIdx.x;
    float acc = 0.f;
    #pragma unroll 8
    for (int i = 0; i < Kk; i++) acc += x[(b * Kk + i) * Dd + d];
    s[b * Dd + d] = acc;
}

__global__ void __launch_bounds__(LSs)
head_kernel(const float* __restrict__ s,
            const float* __restrict__ pw, const float* __restrict__ pb,
            const float* __restrict__ muw, const float* __restrict__ mub,
            const float* __restrict__ spw, const float* __restrict__ spb,
            float* __restrict__ out)
{
    int b = blockIdx.x, n = threadIdx.x;
    __shared__ float ss[Dd];
    __shared__ float sh[LSs];
    ss[n]       = s[b * Dd + n];
    ss[n + 128] = s[b * Dd + n + 128];
    __syncthreads();

    float acc = pb[n];
    #pragma unroll 8
    for (int d = 0; d < Dd; d++) acc = fmaf(ss[d], pw[n * Dd + d], acc);
    sh[n] = 0.5f * acc * (1.0f + erff(acc * 0.7071067811865476f));
    __syncthreads();

    float mu = mub[n], sc = spb[n];
    #pragma unroll 8
    for (int d = 0; d < LSs; d++) {
        mu = fmaf(sh[d], muw[n * LSs + d], mu);
        sc = fmaf(sh[d], spw[n * LSs + d], sc);
    }
    float spv = fmaxf(sc, 0.f) + log1pf(expf(-fabsf(sc)));
    out[b * LSs + n] = mu;
    out[Bb * LSs + b * LSs + n] = spv;
}

// ---------------- launch ----------------
extern "C" void kernel_launch(void* const* d_in, const int* in_sizes, int n_in,
                              void* d_out, int out_size)
{
    (void)in_sizes; (void)n_in; (void)out_size;
    const float* X    = (const float*)d_in[0];
    const float* k_w  = (const float*)d_in[1];
    const float* q_w  = (const float*)d_in[2];
    const float* rw1  = (const float*)d_in[3];
    const float* rb1  = (const float*)d_in[4];
    const float* rw2  = (const float*)d_in[5];
    const float* rb2  = (const float*)d_in[6];
    const float* lng  = (const float*)d_in[7];
    const float* lnb  = (const float*)d_in[8];
    const float* mw1  = (const float*)d_in[9];
    const float* mb1  = (const float*)d_in[10];
    const float* mw2  = (const float*)d_in[11];
    const float* mb2  = (const float*)d_in[12];
    const float* pw   = (const float*)d_in[13];
    const float* pb   = (const float*)d_in[14];
    const float* muw  = (const float*)d_in[15];
    const float* mub  = (const float*)d_in[16];
    const float* spw  = (const float*)d_in[17];
    const float* spb  = (const float*)d_in[18];
    float* out = (float*)d_out;

    static float *px=nullptr,*pqkab=nullptr,*php=nullptr,*pbc=nullptr,*ps=nullptr;
    static __nv_bfloat16 *pxh,*pxl,*pggh,*pggl,*phh,*phl,*pth,*ptl,*pwch,*pwcl,*pw2h,*pw2l;
    if (!px) {
        cudaGetSymbolAddress((void**)&px,    g_x);
        cudaGetSymbolAddress((void**)&pqkab, g_qkab);
        cudaGetSymbolAddress((void**)&php,   g_hp);
        cudaGetSymbolAddress((void**)&pbc,   g_bc);
        cudaGetSymbolAddress((void**)&ps,    g_s);
        cudaGetSymbolAddress((void**)&pxh,   g_xh);
        cudaGetSymbolAddress((void**)&pxl,   g_xl);
        cudaGetSymbolAddress((void**)&pggh,  g_ggh);
        cudaGetSymbolAddress((void**)&pggl,  g_ggl);
        cudaGetSymbolAddress((void**)&phh,   g_hh);
        cudaGetSymbolAddress((void**)&phl,   g_hl);
        cudaGetSymbolAddress((void**)&pth,   g_th);
        cudaGetSymbolAddress((void**)&ptl,   g_tl);
        cudaGetSymbolAddress((void**)&pwch,  g_wch);
        cudaGetSymbolAddress((void**)&pwcl,  g_wcl);
        cudaGetSymbolAddress((void**)&pw2h,  g_w2h);
        cudaGetSymbolAddress((void**)&pw2l,  g_w2l);
        cudaFuncSetAttribute((const void*)tc_gemm<128, 64, 32, 32>,
                             cudaFuncAttributeMaxDynamicSharedMemorySize, SM_BIG);
        cudaFuncSetAttribute((const void*)tc_gemm<64, 32, 32, 16>,
                             cudaFuncAttributeMaxDynamicSharedMemorySize, SM_SMALL);
    }

    copy_conv_kernel<<<(Mm * Dd) / 256, 256>>>(X, px, pxh, pxl, Mm * Dd);

    for (int l = 0; l < NLl; l++) {
        const float* rw1_l = rw1 + l * Dd * 2 * Dd;
        const float* rb1_l = rb1 + l * Dd;
        const float* rw2_l = rw2 + l * Dd * Dd;
        const float* rb2_l = rb2 + l * Dd;
        const float* lg_l  = lng + l * Dd;
        const float* lb_l  = lnb + l * Dd;
        const float* mw1_l = mw1 + l * Dd * Dd;
        const float* mb1_l = mb1 + l * Dd;
        const float* mw2_l = mw2 + l * Dd * Dd;
        const float* mb2_l = mb2 + l * Dd;

        pack_kernel<<<(4 * Dd * Dd) / 256, 256>>>(k_w + l * Dd * Dd, q_w + l * Dd * Dd,
                                                  rw1_l, rb1_l, pwch, pwcl, pbc);
        w2pack_kernel<<<(3 * Dd * Dd) / 256, 256>>>(rw2_l, mw1_l, mw2_l, pw2h, pw2l);

        // fused k|q|a|bb projection: [2048,256] @ [1024,256]^T -> qkab fp32
        tc_gemm<128, 64, 32, 32><<<dim3(16, 16), 256, SM_BIG>>>(
            pxh, pxl, pwch, pwcl, pbc, nullptr, pqkab, QS, nullptr, nullptr, 0);

        attn_kernel<<<dim3(Kk / 4, Bb), 256>>>(pqkab, pggh, pggl);

        // agg proj + residual -> php (fp32)
        tc_gemm<64, 32, 32, 16><<<dim3(8, 32), 128, SM_SMALL>>>(
            pggh, pggl, pw2h, pw2l, rb2_l, px, php, Dd, nullptr, nullptr, 0);
        ln_kernel<<<Mm, 256>>>(php, lg_l, lb_l, phh, phl);
        // mlp1 (gelu) -> t duals only
        tc_gemm<64, 32, 32, 16><<<dim3(8, 32), 128, SM_SMALL>>>(
            phh, phl, pw2h + Dd * Dd, pw2l + Dd * Dd, mb1_l, nullptr, nullptr, Dd, pth, ptl, 1);
        // mlp2 + residual -> px fp32 + duals
        tc_gemm<64, 32, 32, 16><<<dim3(8, 32), 128, SM_SMALL>>>(
            pth, ptl, pw2h + 2 * Dd * Dd, pw2l + 2 * Dd * Dd, mb2_l, px, px, Dd, pxh, pxl, 0);
    }

    pool_kernel<<<Bb, 256>>>(px, ps);
    head_kernel<<<Bb, LSs>>>(ps, pw, pb, muw, mub, spw, spb, out);
}

// round 14
// speedup vs baseline: 1.2509x; 1.0273x over previous
#include <cuda_runtime.h>
#include <cuda_bf16.h>
#include <math.h>
#include <cstdint>

#define Bb   32
#define Kk   64
#define Dd   256
#define LSs  128
#define NLl  2
#define Mm   (Bb*Kk)          // 2048 rows
#define QS   1024             // qkab row stride
#define GK   256              // GEMM K
#define KC   128              // K chunk
#define LDSC 272              // smem row stride bytes for 128 bf16 cols (+16 pad)

// ---------------- scratch (no allocs allowed) ----------------
__device__ float g_x   [Mm*Dd];
__device__ float g_qkab[Mm*QS];
__device__ float g_hp  [Mm*Dd];
__device__ float g_bc  [NLl][4*Dd];
// bf16 hi/lo duals
__device__ __nv_bfloat16 g_xh [Mm*Dd], g_xl [Mm*Dd];
__device__ __nv_bfloat16 g_ggh[Mm*Dd], g_ggl[Mm*Dd];
__device__ __nv_bfloat16 g_hh [Mm*Dd], g_hl [Mm*Dd];
__device__ __nv_bfloat16 g_th [Mm*Dd], g_tl [Mm*Dd];
__device__ __nv_bfloat16 g_wch[NLl][4*Dd*Dd], g_wcl[NLl][4*Dd*Dd];
__device__ __nv_bfloat16 g_w2h[NLl][3*Dd*Dd], g_w2l[NLl][3*Dd*Dd];

// ---------------- fast exact-enough gelu (A&S 7.1.26, |err| < 2e-7) ----------------
__device__ __forceinline__ float gelu_fast(float x) {
    float z = fabsf(x) * 0.7071067811865476f;
    float w = fmaf(z, 0.3275911f, 1.0f);
    float t;
    asm("rcp.approx.f32 %0, %1;" : "=f"(t) : "f"(w));
    float ez = __expf(-z * z);
    float p = fmaf(fmaf(fmaf(fmaf(1.061405429f, t, -1.453152027f), t,
                     1.421413741f), t, -0.284496736f), t, 0.254829592f) * t;
    float e = fmaf(-p, ez, 1.0f);                 // erf(|z|)
    float phi = fmaf(copysignf(e, x), 0.5f, 0.5f);
    return x * phi;
}

__device__ __forceinline__ uint32_t smem_u32(const void* p) {
    uint32_t a;
    asm("{ .reg .u64 t; cvta.to.shared.u64 t, %1; cvt.u32.u64 %0, t; }" : "=r"(a) : "l"(p));
    return a;
}

__device__ __forceinline__ void split_bf16(float v, __nv_bfloat16& h, __nv_bfloat16& l) {
    h = __float2bfloat16(v);
    l = __float2bfloat16(v - __bfloat162float(h));
}
__device__ __forceinline__ void split_pair(float x0, float x1, uint32_t& hp, uint32_t& lp) {
    asm("cvt.rn.bf16x2.f32 %0, %1, %2;" : "=r"(hp) : "f"(x1), "f"(x0));
    float h0 = __uint_as_float(hp << 16);
    float h1 = __uint_as_float(hp & 0xffff0000u);
    asm("cvt.rn.bf16x2.f32 %0, %1, %2;" : "=r"(lp) : "f"(x1 - h1), "f"(x0 - h0));
}

// ---------------- warp MMA primitives ----------------
__device__ __forceinline__ void ldsm_x4(uint32_t* r, uint32_t addr) {
    asm volatile("ldmatrix.sync.aligned.m8n8.x4.shared.b16 {%0,%1,%2,%3}, [%4];"
        : "=r"(r[0]), "=r"(r[1]), "=r"(r[2]), "=r"(r[3]) : "r"(addr));
}
__device__ __forceinline__ void ldsm_x2(uint32_t* r, uint32_t addr) {
    asm volatile("ldmatrix.sync.aligned.m8n8.x2.shared.b16 {%0,%1}, [%2];"
        : "=r"(r[0]), "=r"(r[1]) : "r"(addr));
}
__device__ __forceinline__ void mma_bf16(float* c, const uint32_t* a, const uint32_t* b) {
    asm volatile("mma.sync.aligned.m16n8k16.row.col.f32.bf16.bf16.f32 "
        "{%0,%1,%2,%3}, {%4,%5,%6,%7}, {%8,%9}, {%0,%1,%2,%3};"
        : "+f"(c[0]), "+f"(c[1]), "+f"(c[2]), "+f"(c[3])
        : "r"(a[0]), "r"(a[1]), "r"(a[2]), "r"(a[3]), "r"(b[0]), "r"(b[1]));
}

// cp.async 16B
__device__ __forceinline__ void cpa16(uint32_t sdst, const void* gsrc) {
    asm volatile("cp.async.cg.shared.global [%0], [%1], 16;" :: "r"(sdst), "l"(gsrc));
}
#define CPA_COMMIT() asm volatile("cp.async.commit_group;" ::: "memory")
#define CPA_WAIT()   asm volatile("cp.async.wait_group 0;" ::: "memory")

// stage a KC-wide chunk of a dual tile via cp.async
template<int ROWS, int THREADS>
__device__ __forceinline__ void stage_chunk(const __nv_bfloat16* __restrict__ Gh,
                                            const __nv_bfloat16* __restrict__ Gl,
                                            uint32_t smh, uint32_t sml, int tid) {
    const int ngroups = ROWS * (KC / 8);
    #pragma unroll
    for (int g = tid; g < ngroups; g += THREADS) {
        int row = g >> 4;
        int k0  = (g & 15) * 8;
        uint32_t off = (uint32_t)(row * LDSC + k0 * 2);
        cpa16(smh + off, Gh + (size_t)row * GK + k0);
        cpa16(sml + off, Gl + (size_t)row * GK + k0);
    }
}

template<int TM, int TN>
__device__ __forceinline__ void load_frags(uint32_t kb,
        uint32_t (&ah)[TM][4], uint32_t (&al)[TM][4],
        uint32_t (&bh)[TN][2], uint32_t (&bl)[TN][2],
        const uint32_t* a_base, const uint32_t* b_base,
        uint32_t DA, uint32_t DB) {
    #pragma unroll
    for (int tm = 0; tm < TM; tm++) {
        ldsm_x4(ah[tm], a_base[tm] + kb);
        ldsm_x4(al[tm], a_base[tm] + kb + DA);
    }
    #pragma unroll
    for (int tn = 0; tn < TN; tn++) {
        ldsm_x2(bh[tn], b_base[tn] + kb);
        ldsm_x2(bl[tn], b_base[tn] + kb + DB);
    }
}

// ---------------- bf16x3 GEMM: C = A[M,256] @ Bw[N,256]^T (+bias)(+gelu)(+resid) ----
// CTA: BM x BN tile; K chunked (2 x 128). Warp tile WM x WN; TM=WM/16, TN=WN/8.
template<int BM, int BN, int WM, int WN>
__global__ void __launch_bounds__((BM/WM)*(BN/WN)*32)
tc_gemm(const __nv_bfloat16* __restrict__ Ah, const __nv_bfloat16* __restrict__ Al,
        const __nv_bfloat16* __restrict__ Bh, const __nv_bfloat16* __restrict__ Bl,
        const float* __restrict__ bias, const float* __restrict__ resid,
        float* __restrict__ Cf, int ldc,
        __nv_bfloat16* __restrict__ Ch, __nv_bfloat16* __restrict__ Cl,
        int do_gelu)
{
    constexpr int TM = WM / 16, TN = WN / 8;
    constexpr int WARPS_N = BN / WN;
    constexpr int THREADS = (BM / WM) * (BN / WN) * 32;
    constexpr int SM_AH = 0;
    constexpr int SM_AL = BM * LDSC;
    constexpr int SM_BH = 2 * BM * LDSC;
    constexpr int SM_BL = SM_BH + BN * LDSC;

    extern __shared__ char sm[];
    uint32_t smb = smem_u32(sm);
    const int tid = threadIdx.x, lane = tid & 31, wid = tid >> 5;
    const int warp_m = wid / WARPS_N, warp_n = wid % WARPS_N;
    const int bm = blockIdx.y * BM, bn = blockIdx.x * BN;

    uint32_t a_base[TM], b_base[TN];
    #pragma unroll
    for (int tm = 0; tm < TM; tm++)
        a_base[tm] = smb + SM_AH
                   + (uint32_t)((warp_m * WM + tm * 16 + (lane & 15)) * LDSC)
                   + (uint32_t)((lane >> 4) * 16);
    #pragma unroll
    for (int tn = 0; tn < TN; tn++)
        b_base[tn] = smb + SM_BH
                   + (uint32_t)((warp_n * WN + tn * 8 + (lane & 7)) * LDSC)
                   + (uint32_t)(((lane >> 3) & 1) * 16);

    const uint32_t DA = SM_AL - SM_AH;
    const uint32_t DB = SM_BL - SM_BH;

    float acc[TM][TN][4];
    #pragma unroll
    for (int i = 0; i < TM; i++)
        #pragma unroll
        for (int j = 0; j < TN; j++)
            #pragma unroll
            for (int e = 0; e < 4; e++) acc[i][j][e] = 0.f;

    #pragma unroll 1
    for (int kc = 0; kc < GK / KC; kc++) {
        if (kc) __syncthreads();   // protect smem before restage
        stage_chunk<BM, THREADS>(Ah + (size_t)bm * GK + kc * KC,
                                 Al + (size_t)bm * GK + kc * KC,
                                 smb + SM_AH, smb + SM_AL, tid);
        stage_chunk<BN, THREADS>(Bh + (size_t)bn * GK + kc * KC,
                                 Bl + (size_t)bn * GK + kc * KC,
                                 smb + SM_BH, smb + SM_BL, tid);
        CPA_COMMIT();
        CPA_WAIT();
        __syncthreads();

        if constexpr (TM <= 2) {
            // double-buffered fragments
            uint32_t ah[2][TM][4], al[2][TM][4], bh[2][TN][2], bl[2][TN][2];
            load_frags<TM, TN>(0, ah[0], al[0], bh[0], bl[0], a_base, b_base, DA, DB);
            #pragma unroll
            for (int ks = 0; ks < KC / 16; ks++) {
                const int cur = ks & 1, nxt = cur ^ 1;
                if (ks < KC / 16 - 1)
                    load_frags<TM, TN>((uint32_t)((ks + 1) * 32),
                                       ah[nxt], al[nxt], bh[nxt], bl[nxt],
                                       a_base, b_base, DA, DB);
                #pragma unroll
                for (int tm = 0; tm < TM; tm++)
                    #pragma unroll
                    for (int tn = 0; tn < TN; tn++)
                        mma_bf16(acc[tm][tn], ah[cur][tm], bh[cur][tn]);
                #pragma unroll
                for (int tm = 0; tm < TM; tm++)
                    #pragma unroll
                    for (int tn = 0; tn < TN; tn++)
                        mma_bf16(acc[tm][tn], ah[cur][tm], bl[cur][tn]);
                #pragma unroll
                for (int tm = 0; tm < TM; tm++)
                    #pragma unroll
                    for (int tn = 0; tn < TN; tn++)
                        mma_bf16(acc[tm][tn], al[cur][tm], bh[cur][tn]);
            }
        } else {
            // single-buffered fragments (high ILP from TM*TN chains)
            uint32_t ah[TM][4], al[TM][4], bh[TN][2], bl[TN][2];
            #pragma unroll
            for (int ks = 0; ks < KC / 16; ks++) {
                load_frags<TM, TN>((uint32_t)(ks * 32), ah, al, bh, bl,
                                   a_base, b_base, DA, DB);
                #pragma unroll
                for (int tm = 0; tm < TM; tm++)
                    #pragma unroll
                    for (int tn = 0; tn < TN; tn++)
                        mma_bf16(acc[tm][tn], ah[tm], bh[tn]);
                #pragma unroll
                for (int tm = 0; tm < TM; tm++)
                    #pragma unroll
                    for (int tn = 0; tn < TN; tn++)
                        mma_bf16(acc[tm][tn], ah[tm], bl[tn]);
                #pragma unroll
                for (int tm = 0; tm < TM; tm++)
                    #pragma unroll
                    for (int tn = 0; tn < TN; tn++)
                        mma_bf16(acc[tm][tn], al[tm], bh[tn]);
            }
        }
    }

    // epilogue
    #pragma unroll
    for (int tm = 0; tm < TM; tm++) {
        int r0 = bm + warp_m * WM + tm * 16 + (lane >> 2);
        #pragma unroll
        for (int tn = 0; tn < TN; tn++) {
            int c = bn + warp_n * WN + tn * 8 + (lane & 3) * 2;
            #pragma unroll
            for (int h = 0; h < 2; h++) {
                int r = r0 + h * 8;
                float x0 = acc[tm][tn][h * 2 + 0];
                float x1 = acc[tm][tn][h * 2 + 1];
                if (bias)  { x0 += bias[c]; x1 += bias[c + 1]; }
                if (do_gelu) { x0 = gelu_fast(x0); x1 = gelu_fast(x1); }
                if (resid) {
                    float2 rr = *(const float2*)(resid + (size_t)r * ldc + c);
                    x0 += rr.x; x1 += rr.y;
                }
                if (Cf) *(float2*)(Cf + (size_t)r * ldc + c) = make_float2(x0, x1);
                if (Ch) {
                    uint32_t hp, lp;
                    split_pair(x0, x1, hp, lp);
                    *(uint32_t*)(Ch + (size_t)r * Dd + c) = hp;
                    *(uint32_t*)(Cl + (size_t)r * Dd + c) = lp;
                }
            }
        }
    }
}

// smem sizes
#define SM_BIG   (2 * (128 + 64) * LDSC)   // 104448 -> 2 CTAs/SM
#define SM_SMALL (2 * (64 + 64) * LDSC)    // 69632  -> 3 CTAs/SM

// ---------------- producer/conversion kernels ----------------
__global__ void copy_conv_kernel(const float* __restrict__ src, float* __restrict__ dst,
                                 __nv_bfloat16* __restrict__ dh, __nv_bfloat16* __restrict__ dl,
                                 int n) {
    int i = blockIdx.x * blockDim.x + threadIdx.x;
    if (i < n) {
        float v = src[i];
        dst[i] = v;
        __nv_bfloat16 h, l; split_bf16(v, h, l);
        dh[i] = h; dl[i] = l;
    }
}

// pack combined weights (duals): rows [0:256)=k_w, [256:512)=q_w, [512:768)=W1a+W1b, [768:1024)=W1b
__global__ void pack_kernel(const float* __restrict__ kw, const float* __restrict__ qw,
                            const float* __restrict__ w1, const float* __restrict__ rb1,
                            __nv_bfloat16* __restrict__ wch, __nv_bfloat16* __restrict__ wcl,
                            float* __restrict__ bc) {
    int i = blockIdx.x * blockDim.x + threadIdx.x;
    int r = i >> 8, c = i & 255;
    float v;
    if (r < 256)      v = kw[r * Dd + c];
    else if (r < 512) v = qw[(r - 256) * Dd + c];
    else if (r < 768) { int d = r - 512; v = w1[d * 2 * Dd + c] + w1[d * 2 * Dd + Dd + c]; }
    else              { int d = r - 768; v = w1[d * 2 * Dd + Dd + c]; }
    __nv_bfloat16 h, l; split_bf16(v, h, l);
    wch[i] = h; wcl[i] = l;
    if (i < 4 * Dd) bc[i] = (i >= 512 && i < 768) ? rb1[i - 512] : 0.f;
}

// pack rw2|mw1|mw2 as dual slabs
__global__ void w2pack_kernel(const float* __restrict__ rw2, const float* __restrict__ mw1,
                              const float* __restrict__ mw2,
                              __nv_bfloat16* __restrict__ w2h, __nv_bfloat16* __restrict__ w2l) {
    int i = blockIdx.x * blockDim.x + threadIdx.x;   // [0, 3*65536)
    int s = i >> 16, o = i & 65535;
    const float* src = (s == 0) ? rw2 : ((s == 1) ? mw1 : mw2);
    float v = src[o];
    __nv_bfloat16 h, l; split_bf16(v, h, l);
    w2h[i] = h; w2l[i] = l;
}

// ---------------- attention + gelu aggregation, 4 queries per block ----------------
// qkab row layout: [k(256) | q(256) | a(256) | bb(256)]
__global__ void __launch_bounds__(256)
attn_kernel(const float* __restrict__ qkab,
            __nv_bfloat16* __restrict__ ggh, __nv_bfloat16* __restrict__ ggl)
{
    const int b = blockIdx.y, i0 = blockIdx.x * 4;
    const int tid = threadIdx.x;
    const int lane = tid & 31, warp = tid >> 5;

    __shared__ float sq[4][Dd];
    __shared__ float sa[4][Dd];
    __shared__ float sl[4][Kk];
    __shared__ float sp[4][Kk];

    const float* base = qkab + (size_t)b * Kk * QS;

    #pragma unroll
    for (int ii = 0; ii < 4; ii++) {
        const float* row = base + (size_t)(i0 + ii) * QS;
        sq[ii][tid] = row[256 + tid];
        sa[ii][tid] = row[512 + tid];
    }
    __syncthreads();

    for (int j = warp; j < Kk; j += 8) {
        const float* kj = base + (size_t)j * QS;
        float kv[8];
        #pragma unroll
        for (int m = 0; m < 8; m++) kv[m] = kj[lane + 32 * m];
        #pragma unroll
        for (int ii = 0; ii < 4; ii++) {
            float t = 0.f;
            #pragma unroll
            for (int m = 0; m < 8; m++) t = fmaf(sq[ii][lane + 32 * m], kv[m], t);
            #pragma unroll
            for (int o = 16; o; o >>= 1) t += __shfl_xor_sync(0xffffffffu, t, o);
            if (lane == 0) sl[ii][j] = t * 0.0625f;   // D^-0.5
        }
    }
    __syncthreads();

    if (warp < 4) {
        float v0 = sl[warp][lane], v1 = sl[warp][lane + 32];
        float m = fmaxf(v0, v1);
        #pragma unroll
        for (int o = 16; o; o >>= 1) m = fmaxf(m, __shfl_xor_sync(0xffffffffu, m, o));
        float e0 = __expf(v0 - m), e1 = __expf(v1 - m);
        float s = e0 + e1;
        #pragma unroll
        for (int o = 16; o; o >>= 1) s += __shfl_xor_sync(0xffffffffu, s, o);
        float inv = 1.f / s;
        sp[warp][lane] = e0 * inv; sp[warp][lane + 32] = e1 * inv;
    }
    __syncthreads();

    const float a0 = sa[0][tid], a1 = sa[1][tid], a2 = sa[2][tid], a3 = sa[3][tid];
    float c0 = 0.f, c1 = 0.f, c2 = 0.f, c3 = 0.f;
    const float* bbp = base + 768 + tid;
    #pragma unroll 4
    for (int j = 0; j < Kk; j++) {
        float bb = __ldg(bbp + (size_t)j * QS);
        c0 = fmaf(sp[0][j], gelu_fast(a0 - bb), c0);
        c1 = fmaf(sp[1][j], gelu_fast(a1 - bb), c1);
        c2 = fmaf(sp[2][j], gelu_fast(a2 - bb), c2);
        c3 = fmaf(sp[3][j], gelu_fast(a3 - bb), c3);
    }
    float cc[4] = {c0, c1, c2, c3};
    #pragma unroll
    for (int ii = 0; ii < 4; ii++) {
        size_t idx = (size_t)(b * Kk + i0 + ii) * Dd + tid;
        __nv_bfloat16 h, l; split_bf16(cc[ii], h, l);
        ggh[idx] = h; ggl[idx] = l;
    }
}

// ---------------- layernorm over D=256 -> duals only ----------------
__device__ __forceinline__ float blocksum256(float v, float* red) {
    int lane = threadIdx.x & 31, w = threadIdx.x >> 5;
    #pragma unroll
    for (int o = 16; o; o >>= 1) v += __shfl_xor_sync(0xffffffffu, v, o);
    __syncthreads();
    if (lane == 0) red[w] = v;
    __syncthreads();
    float t = red[0];
    #pragma unroll
    for (int i = 1; i < 8; i++) t += red[i];
    return t;
}

__global__ void __launch_bounds__(256)
ln_kernel(const float* __restrict__ in, const float* __restrict__ gam,
          const float* __restrict__ bet,
          __nv_bfloat16* __restrict__ outh, __nv_bfloat16* __restrict__ outl)
{
    __shared__ float red[8];
    int r = blockIdx.x, tid = threadIdx.x;
    float v = in[r * Dd + tid];
    float mean = blocksum256(v, red) * (1.f / Dd);
    float dv = v - mean;
    float var = blocksum256(dv * dv, red) * (1.f / Dd);
    float o = dv * rsqrtf(var + 1e-5f) * gam[tid] + bet[tid];
    __nv_bfloat16 h, l; split_bf16(o, h, l);
    outh[r * Dd + tid] = h;
    outl[r * Dd + tid] = l;
}

// ---------------- fused pool + heads ----------------
__global__ void __launch_bounds__(256)
pool_head_kernel(const float* __restrict__ x,
                 const float* __restrict__ pw, const float* __restrict__ pb,
                 const float* __restrict__ muw, const float* __restrict__ mub,
                 const float* __restrict__ spw, const float* __restrict__ spb,
                 float* __restrict__ out)
{
    int b = blockIdx.x, tid = threadIdx.x;
    __shared__ float ss[Dd];
    __shared__ float sh[LSs];

    float acc = 0.f;
    #pragma unroll 8
    for (int i = 0; i < Kk; i++) acc += x[(b * Kk + i) * Dd + tid];
    ss[tid] = acc;
    __syncthreads();

    if (tid < LSs) {
        float a = pb[tid];
        #pragma unroll 8
        for (int d = 0; d < Dd; d++) a = fmaf(ss[d], pw[tid * Dd + d], a);
        sh[tid] = 0.5f * a * (1.0f + erff(a * 0.7071067811865476f));
    }
    __syncthreads();

    if (tid < LSs) {
        float mu = mub[tid], sc = spb[tid];
        #pragma unroll 8
        for (int d = 0; d < LSs; d++) {
            mu = fmaf(sh[d], muw[tid * LSs + d], mu);
            sc = fmaf(sh[d], spw[tid * LSs + d], sc);
        }
        float spv = fmaxf(sc, 0.f) + log1pf(expf(-fabsf(sc)));
        out[b * LSs + tid] = mu;
        out[Bb * LSs + b * LSs + tid] = spv;
    }
}

// ---------------- launch ----------------
extern "C" void kernel_launch(void* const* d_in, const int* in_sizes, int n_in,
                              void* d_out, int out_size)
{
    (void)in_sizes; (void)n_in; (void)out_size;
    const float* X    = (const float*)d_in[0];
    const float* k_w  = (const float*)d_in[1];
    const float* q_w  = (const float*)d_in[2];
    const float* rw1  = (const float*)d_in[3];
    const float* rb1  = (const float*)d_in[4];
    const float* rw2  = (const float*)d_in[5];
    const float* rb2  = (const float*)d_in[6];
    const float* lng  = (const float*)d_in[7];
    const float* lnb  = (const float*)d_in[8];
    const float* mw1  = (const float*)d_in[9];
    const float* mb1  = (const float*)d_in[10];
    const float* mw2  = (const float*)d_in[11];
    const float* mb2  = (const float*)d_in[12];
    const float* pw   = (const float*)d_in[13];
    const float* pb   = (const float*)d_in[14];
    const float* muw  = (const float*)d_in[15];
    const float* mub  = (const float*)d_in[16];
    const float* spw  = (const float*)d_in[17];
    const float* spb  = (const float*)d_in[18];
    float* out = (float*)d_out;

    static float *px=nullptr,*pqkab=nullptr,*php=nullptr,*pbc=nullptr;
    static __nv_bfloat16 *pxh,*pxl,*pggh,*pggl,*phh,*phl,*pth,*ptl,*pwch,*pwcl,*pw2h,*pw2l;
    if (!px) {
        cudaGetSymbolAddress((void**)&px,    g_x);
        cudaGetSymbolAddress((void**)&pqkab, g_qkab);
        cudaGetSymbolAddress((void**)&php,   g_hp);
        cudaGetSymbolAddress((void**)&pbc,   g_bc);
        cudaGetSymbolAddress((void**)&pxh,   g_xh);
        cudaGetSymbolAddress((void**)&pxl,   g_xl);
        cudaGetSymbolAddress((void**)&pggh,  g_ggh);
        cudaGetSymbolAddress((void**)&pggl,  g_ggl);
        cudaGetSymbolAddress((void**)&phh,   g_hh);
        cudaGetSymbolAddress((void**)&phl,   g_hl);
        cudaGetSymbolAddress((void**)&pth,   g_th);
        cudaGetSymbolAddress((void**)&ptl,   g_tl);
        cudaGetSymbolAddress((void**)&pwch,  g_wch);
        cudaGetSymbolAddress((void**)&pwcl,  g_wcl);
        cudaGetSymbolAddress((void**)&pw2h,  g_w2h);
        cudaGetSymbolAddress((void**)&pw2l,  g_w2l);
        cudaFuncSetAttribute((const void*)tc_gemm<128, 64, 64, 32>,
                             cudaFuncAttributeMaxDynamicSharedMemorySize, SM_BIG);
        cudaFuncSetAttribute((const void*)tc_gemm<64, 64, 32, 32>,
                             cudaFuncAttributeMaxDynamicSharedMemorySize, SM_SMALL);
    }

    // input conversion + all weight packing upfront (independent of layer chain)
    copy_conv_kernel<<<(Mm * Dd) / 256, 256>>>(X, px, pxh, pxl, Mm * Dd);
    for (int l = 0; l < NLl; l++) {
        pack_kernel<<<(4 * Dd * Dd) / 256, 256>>>(
            k_w + l * Dd * Dd, q_w + l * Dd * Dd,
            rw1 + l * Dd * 2 * Dd, rb1 + l * Dd,
            pwch + l * 4 * Dd * Dd, pwcl + l * 4 * Dd * Dd, pbc + l * 4 * Dd);
        w2pack_kernel<<<(3 * Dd * Dd) / 256, 256>>>(
            rw2 + l * Dd * Dd, mw1 + l * Dd * Dd, mw2 + l * Dd * Dd,
            pw2h + l * 3 * Dd * Dd, pw2l + l * 3 * Dd * Dd);
    }

    for (int l = 0; l < NLl; l++) {
        const float* rb2_l = rb2 + l * Dd;
        const float* lg_l  = lng + l * Dd;
        const float* lb_l  = lnb + l * Dd;
        const float* mb1_l = mb1 + l * Dd;
        const float* mb2_l = mb2 + l * Dd;
        __nv_bfloat16* wch_l = pwch + l * 4 * Dd * Dd;
        __nv_bfloat16* wcl_l = pwcl + l * 4 * Dd * Dd;
        __nv_bfloat16* w2h_l = pw2h + l * 3 * Dd * Dd;
        __nv_bfloat16* w2l_l = pw2l + l * 3 * Dd * Dd;
        float* bc_l = pbc + l * 4 * Dd;

        // fused k|q|a|bb projection: [2048,256] @ [1024,256]^T -> qkab fp32
        tc_gemm<128, 64, 64, 32><<<dim3(16, 16), 128, SM_BIG>>>(
            pxh, pxl, wch_l, wcl_l, bc_l, nullptr, pqkab, QS, nullptr, nullptr, 0);

        attn_kernel<<<dim3(Kk / 4, Bb), 256>>>(pqkab, pggh, pggl);

        // agg proj + residual -> php (fp32)
        tc_gemm<64, 64, 32, 32><<<dim3(4, 32), 128, SM_SMALL>>>(
            pggh, pggl, w2h_l, w2l_l, rb2_l, px, php, Dd, nullptr, nullptr, 0);
        ln_kernel<<<Mm, 256>>>(php, lg_l, lb_l, phh, phl);
        // mlp1 (gelu) -> t duals only
        tc_gemm<64, 64, 32, 32><<<dim3(4, 32), 128, SM_SMALL>>>(
            phh, phl, w2h_l + Dd * Dd, w2l_l + Dd * Dd, mb1_l, nullptr, nullptr, Dd, pth, ptl, 1);
        // mlp2 + residual -> px fp32 + duals
        tc_gemm<64, 64, 32, 32><<<dim3(4, 32), 128, SM_SMALL>>>(
            pth, ptl, w2h_l + 2 * Dd * Dd, w2l_l + 2 * Dd * Dd, mb2_l, px, px, Dd, pxh, pxl, 0);
    }

    pool_head_kernel<<<Bb, 256>>>(px, pw, pb, muw, mub, spw, spb, out);
}

// round 15
// speedup vs baseline: 1.2992x; 1.0386x over previous
#include <cuda_runtime.h>
#include <cuda_bf16.h>
#include <math.h>
#include <cstdint>

#define Bb   32
#define Kk   64
#define Dd   256
#define LSs  128
#define NLl  2
#define Mm   (Bb*Kk)          // 2048 rows
#define QS   1024             // qkab row stride
#define GK   256              // GEMM K
#define KC   64               // K chunk (pipelined)
#define LDSC 144              // smem row stride bytes for 64 bf16 cols (+16 pad)

// ---------------- scratch (no allocs allowed) ----------------
__device__ float g_x   [Mm*Dd];
__device__ float g_qkab[Mm*QS];
__device__ float g_hp  [Mm*Dd];
__device__ float g_bc  [NLl][4*Dd];
// bf16 hi/lo duals
__device__ __nv_bfloat16 g_xh [Mm*Dd], g_xl [Mm*Dd];
__device__ __nv_bfloat16 g_ggh[Mm*Dd], g_ggl[Mm*Dd];
__device__ __nv_bfloat16 g_hh [Mm*Dd], g_hl [Mm*Dd];
__device__ __nv_bfloat16 g_th [Mm*Dd], g_tl [Mm*Dd];
__device__ __nv_bfloat16 g_wch[NLl][4*Dd*Dd], g_wcl[NLl][4*Dd*Dd];
__device__ __nv_bfloat16 g_w2h[NLl][3*Dd*Dd], g_w2l[NLl][3*Dd*Dd];

// ---------------- fast exact-enough gelu (A&S 7.1.26, |err| < 2e-7) ----------------
__device__ __forceinline__ float gelu_fast(float x) {
    float z = fabsf(x) * 0.7071067811865476f;
    float w = fmaf(z, 0.3275911f, 1.0f);
    float t;
    asm("rcp.approx.f32 %0, %1;" : "=f"(t) : "f"(w));
    float ez = __expf(-z * z);
    float p = fmaf(fmaf(fmaf(fmaf(1.061405429f, t, -1.453152027f), t,
                     1.421413741f), t, -0.284496736f), t, 0.254829592f) * t;
    float e = fmaf(-p, ez, 1.0f);                 // erf(|z|)
    float phi = fmaf(copysignf(e, x), 0.5f, 0.5f);
    return x * phi;
}

__device__ __forceinline__ uint32_t smem_u32(const void* p) {
    uint32_t a;
    asm("{ .reg .u64 t; cvta.to.shared.u64 t, %1; cvt.u32.u64 %0, t; }" : "=r"(a) : "l"(p));
    return a;
}

__device__ __forceinline__ void split_bf16(float v, __nv_bfloat16& h, __nv_bfloat16& l) {
    h = __float2bfloat16(v);
    l = __float2bfloat16(v - __bfloat162float(h));
}
__device__ __forceinline__ void split_pair(float x0, float x1, uint32_t& hp, uint32_t& lp) {
    asm("cvt.rn.bf16x2.f32 %0, %1, %2;" : "=r"(hp) : "f"(x1), "f"(x0));
    float h0 = __uint_as_float(hp << 16);
    float h1 = __uint_as_float(hp & 0xffff0000u);
    asm("cvt.rn.bf16x2.f32 %0, %1, %2;" : "=r"(lp) : "f"(x1 - h1), "f"(x0 - h0));
}

// ---------------- warp MMA primitives ----------------
__device__ __forceinline__ void ldsm_x4(uint32_t* r, uint32_t addr) {
    asm volatile("ldmatrix.sync.aligned.m8n8.x4.shared.b16 {%0,%1,%2,%3}, [%4];"
        : "=r"(r[0]), "=r"(r[1]), "=r"(r[2]), "=r"(r[3]) : "r"(addr));
}
__device__ __forceinline__ void ldsm_x2(uint32_t* r, uint32_t addr) {
    asm volatile("ldmatrix.sync.aligned.m8n8.x2.shared.b16 {%0,%1}, [%2];"
        : "=r"(r[0]), "=r"(r[1]) : "r"(addr));
}
__device__ __forceinline__ void mma_bf16(float* c, const uint32_t* a, const uint32_t* b) {
    asm volatile("mma.sync.aligned.m16n8k16.row.col.f32.bf16.bf16.f32 "
        "{%0,%1,%2,%3}, {%4,%5,%6,%7}, {%8,%9}, {%0,%1,%2,%3};"
        : "+f"(c[0]), "+f"(c[1]), "+f"(c[2]), "+f"(c[3])
        : "r"(a[0]), "r"(a[1]), "r"(a[2]), "r"(a[3]), "r"(b[0]), "r"(b[1]));
}

// cp.async 16B
__device__ __forceinline__ void cpa16(uint32_t sdst, const void* gsrc) {
    asm volatile("cp.async.cg.shared.global [%0], [%1], 16;" :: "r"(sdst), "l"(gsrc));
}
#define CPA_COMMIT() asm volatile("cp.async.commit_group;" ::: "memory")
#define CPA_WAIT_0() asm volatile("cp.async.wait_group 0;" ::: "memory")
#define CPA_WAIT_1() asm volatile("cp.async.wait_group 1;" ::: "memory")

// stage a KC-wide chunk of a dual tile via cp.async
template<int ROWS, int THREADS>
__device__ __forceinline__ void stage_chunk(const __nv_bfloat16* __restrict__ Gh,
                                            const __nv_bfloat16* __restrict__ Gl,
                                            uint32_t smh, uint32_t sml, int tid) {
    const int ngroups = ROWS * (KC / 8);    // KC/8 = 8 groups per row
    #pragma unroll
    for (int g = tid; g < ngroups; g += THREADS) {
        int row = g >> 3;
        int k0  = (g & 7) * 8;
        uint32_t off = (uint32_t)(row * LDSC + k0 * 2);
        cpa16(smh + off, Gh + (size_t)row * GK + k0);
        cpa16(sml + off, Gl + (size_t)row * GK + k0);
    }
}

template<int TM, int TN>
__device__ __forceinline__ void load_frags(uint32_t sb, uint32_t kb,
        uint32_t (&ah)[TM][4], uint32_t (&al)[TM][4],
        uint32_t (&bh)[TN][2], uint32_t (&bl)[TN][2],
        const uint32_t* a_off, const uint32_t* b_off,
        uint32_t DA, uint32_t DB) {
    #pragma unroll
    for (int tm = 0; tm < TM; tm++) {
        ldsm_x4(ah[tm], sb + a_off[tm] + kb);
        ldsm_x4(al[tm], sb + a_off[tm] + kb + DA);
    }
    #pragma unroll
    for (int tn = 0; tn < TN; tn++) {
        ldsm_x2(bh[tn], sb + b_off[tn] + kb);
        ldsm_x2(bl[tn], sb + b_off[tn] + kb + DB);
    }
}

// ---------------- bf16x3 GEMM with 2-stage smem pipeline ----------------
// C = A[M,256] @ Bw[N,256]^T (+bias)(+gelu)(+resid). CTA: BM x BN.
template<int BM, int BN, int WM, int WN>
__global__ void __launch_bounds__((BM/WM)*(BN/WN)*32)
tc_gemm(const __nv_bfloat16* __restrict__ Ah, const __nv_bfloat16* __restrict__ Al,
        const __nv_bfloat16* __restrict__ Bh, const __nv_bfloat16* __restrict__ Bl,
        const float* __restrict__ bias, const float* __restrict__ resid,
        float* __restrict__ Cf, int ldc,
        __nv_bfloat16* __restrict__ Ch, __nv_bfloat16* __restrict__ Cl,
        int do_gelu)
{
    constexpr int TM = WM / 16, TN = WN / 8;
    constexpr int WARPS_N = BN / WN;
    constexpr int THREADS = (BM / WM) * (BN / WN) * 32;
    constexpr int NKC = GK / KC;          // 4 chunks
    constexpr int KSTEPS = KC / 16;       // 4
    constexpr uint32_t OF_AH = 0;
    constexpr uint32_t OF_AL = (uint32_t)BM * LDSC;
    constexpr uint32_t OF_BH = 2u * BM * LDSC;
    constexpr uint32_t OF_BL = 2u * BM * LDSC + (uint32_t)BN * LDSC;
    constexpr uint32_t SBUF  = 2u * (BM + BN) * LDSC;

    extern __shared__ char sm[];
    uint32_t smb = smem_u32(sm);
    const int tid = threadIdx.x, lane = tid & 31, wid = tid >> 5;
    const int warp_m = wid / WARPS_N, warp_n = wid % WARPS_N;
    const int bm = blockIdx.y * BM, bn = blockIdx.x * BN;

    uint32_t a_off[TM], b_off[TN];
    #pragma unroll
    for (int tm = 0; tm < TM; tm++)
        a_off[tm] = OF_AH + (uint32_t)((warp_m * WM + tm * 16 + (lane & 15)) * LDSC)
                  + (uint32_t)((lane >> 4) * 16);
    #pragma unroll
    for (int tn = 0; tn < TN; tn++)
        b_off[tn] = OF_BH + (uint32_t)((warp_n * WN + tn * 8 + (lane & 7)) * LDSC)
                  + (uint32_t)(((lane >> 3) & 1) * 16);

    const uint32_t DA = (uint32_t)BM * LDSC;   // AH->AL
    const uint32_t DB = (uint32_t)BN * LDSC;   // BH->BL

    float acc[TM][TN][4];
    #pragma unroll
    for (int i = 0; i < TM; i++)
        #pragma unroll
        for (int j = 0; j < TN; j++)
            #pragma unroll
            for (int e = 0; e < 4; e++) acc[i][j][e] = 0.f;

    const __nv_bfloat16* Abh = Ah + (size_t)bm * GK;
    const __nv_bfloat16* Abl = Al + (size_t)bm * GK;
    const __nv_bfloat16* Bbh = Bh + (size_t)bn * GK;
    const __nv_bfloat16* Bbl = Bl + (size_t)bn * GK;

    // prologue: stage chunk 0 into buffer 0
    {
        uint32_t base = smb;
        stage_chunk<BM, THREADS>(Abh, Abl, base + OF_AH, base + OF_AL, tid);
        stage_chunk<BN, THREADS>(Bbh, Bbl, base + OF_BH, base + OF_BL, tid);
        CPA_COMMIT();
    }

    #pragma unroll 1
    for (int kc = 0; kc < NKC; kc++) {
        const uint32_t sb = smb + (uint32_t)(kc & 1) * SBUF;
        if (kc + 1 < NKC) {
            // prefetch next chunk into other buffer (safe: its readers synced last iter)
            uint32_t base = smb + (uint32_t)((kc + 1) & 1) * SBUF;
            stage_chunk<BM, THREADS>(Abh + (kc + 1) * KC, Abl + (kc + 1) * KC,
                                     base + OF_AH, base + OF_AL, tid);
            stage_chunk<BN, THREADS>(Bbh + (kc + 1) * KC, Bbl + (kc + 1) * KC,
                                     base + OF_BH, base + OF_BL, tid);
            CPA_COMMIT();
            CPA_WAIT_1();     // chunk kc landed (prefetch may still be in flight)
        } else {
            CPA_WAIT_0();
        }
        __syncthreads();

        if constexpr (TM <= 2) {
            // double-buffered fragments
            uint32_t ah[2][TM][4], al[2][TM][4], bh[2][TN][2], bl[2][TN][2];
            load_frags<TM, TN>(sb, 0, ah[0], al[0], bh[0], bl[0], a_off, b_off, DA, DB);
            #pragma unroll
            for (int ks = 0; ks < KSTEPS; ks++) {
                const int cur = ks & 1, nxt = cur ^ 1;
                if (ks < KSTEPS - 1)
                    load_frags<TM, TN>(sb, (uint32_t)((ks + 1) * 32),
                                       ah[nxt], al[nxt], bh[nxt], bl[nxt],
                                       a_off, b_off, DA, DB);
                #pragma unroll
                for (int tm = 0; tm < TM; tm++)
                    #pragma unroll
                    for (int tn = 0; tn < TN; tn++)
                        mma_bf16(acc[tm][tn], ah[cur][tm], bh[cur][tn]);
                #pragma unroll
                for (int tm = 0; tm < TM; tm++)
                    #pragma unroll
                    for (int tn = 0; tn < TN; tn++)
                        mma_bf16(acc[tm][tn], ah[cur][tm], bl[cur][tn]);
                #pragma unroll
                for (int tm = 0; tm < TM; tm++)
                    #pragma unroll
                    for (int tn = 0; tn < TN; tn++)
                        mma_bf16(acc[tm][tn], al[cur][tm], bh[cur][tn]);
            }
        } else {
            // single-buffered fragments (ILP from TM*TN chains)
            uint32_t ah[TM][4], al[TM][4], bh[TN][2], bl[TN][2];
            #pragma unroll
            for (int ks = 0; ks < KSTEPS; ks++) {
                load_frags<TM, TN>(sb, (uint32_t)(ks * 32), ah, al, bh, bl,
                                   a_off, b_off, DA, DB);
                #pragma unroll
                for (int tm = 0; tm < TM; tm++)
                    #pragma unroll
                    for (int tn = 0; tn < TN; tn++)
                        mma_bf16(acc[tm][tn], ah[tm], bh[tn]);
                #pragma unroll
                for (int tm = 0; tm < TM; tm++)
                    #pragma unroll
                    for (int tn = 0; tn < TN; tn++)
                        mma_bf16(acc[tm][tn], ah[tm], bl[tn]);
                #pragma unroll
                for (int tm = 0; tm < TM; tm++)
                    #pragma unroll
                    for (int tn = 0; tn < TN; tn++)
                        mma_bf16(acc[tm][tn], al[tm], bh[tn]);
            }
        }
        __syncthreads();   // all reads of buffer (kc&1) done before it is restaged
    }

    // epilogue
    #pragma unroll
    for (int tm = 0; tm < TM; tm++) {
        int r0 = bm + warp_m * WM + tm * 16 + (lane >> 2);
        #pragma unroll
        for (int tn = 0; tn < TN; tn++) {
            int c = bn + warp_n * WN + tn * 8 + (lane & 3) * 2;
            #pragma unroll
            for (int h = 0; h < 2; h++) {
                int r = r0 + h * 8;
                float x0 = acc[tm][tn][h * 2 + 0];
                float x1 = acc[tm][tn][h * 2 + 1];
                if (bias)  { x0 += bias[c]; x1 += bias[c + 1]; }
                if (do_gelu) { x0 = gelu_fast(x0); x1 = gelu_fast(x1); }
                if (resid) {
                    float2 rr = *(const float2*)(resid + (size_t)r * ldc + c);
                    x0 += rr.x; x1 += rr.y;
                }
                if (Cf) *(float2*)(Cf + (size_t)r * ldc + c) = make_float2(x0, x1);
                if (Ch) {
                    uint32_t hp, lp;
                    split_pair(x0, x1, hp, lp);
                    *(uint32_t*)(Ch + (size_t)r * Dd + c) = hp;
                    *(uint32_t*)(Cl + (size_t)r * Dd + c) = lp;
                }
            }
        }
    }
}

// smem sizes (2 pipeline stages)
#define SM_BIG   (2 * 2 * (128 + 64) * LDSC)   // 110592 -> 2 CTAs/SM
#define SM_SMALL (2 * 2 * (64 + 32) * LDSC)    // 55296  -> 4 CTAs/SM

// ---------------- fused prep: input conversion + all weight packing ----------------
// blocks [0,2048): copy_conv; [2048,4096): pack (2 layers); [4096,5632): w2pack (2 layers)
__global__ void __launch_bounds__(256)
prep_kernel(const float* __restrict__ X,
            const float* __restrict__ k_w, const float* __restrict__ q_w,
            const float* __restrict__ rw1, const float* __restrict__ rb1,
            const float* __restrict__ rw2, const float* __restrict__ mw1,
            const float* __restrict__ mw2,
            float* __restrict__ px,
            __nv_bfloat16* __restrict__ pxh, __nv_bfloat16* __restrict__ pxl,
            __nv_bfloat16* __restrict__ wch, __nv_bfloat16* __restrict__ wcl,
            float* __restrict__ bc,
            __nv_bfloat16* __restrict__ w2h, __nv_bfloat16* __restrict__ w2l)
{
    int blk = blockIdx.x, tid = threadIdx.x;
    if (blk < 2048) {
        int i = blk * 256 + tid;
        float v = X[i];
        px[i] = v;
        __nv_bfloat16 h, l; split_bf16(v, h, l);
        pxh[i] = h; pxl[i] = l;
    } else if (blk < 4096) {
        int b2 = blk - 2048;
        int l = b2 >> 10;
        int i = (b2 & 1023) * 256 + tid;       // [0, 262144)
        const float* kw = k_w + l * Dd * Dd;
        const float* qw = q_w + l * Dd * Dd;
        const float* w1 = rw1 + l * Dd * 2 * Dd;
        int r = i >> 8, c = i & 255;
        float v;
        if (r < 256)      v = kw[r * Dd + c];
        else if (r < 512) v = qw[(r - 256) * Dd + c];
        else if (r < 768) { int d = r - 512; v = w1[d * 2 * Dd + c] + w1[d * 2 * Dd + Dd + c]; }
        else              { int d = r - 768; v = w1[d * 2 * Dd + Dd + c]; }
        __nv_bfloat16 h, lo; split_bf16(v, h, lo);
        wch[l * 4 * Dd * Dd + i] = h;
        wcl[l * 4 * Dd * Dd + i] = lo;
        if (i < 4 * Dd)
            bc[l * 4 * Dd + i] = (i >= 512 && i < 768) ? rb1[l * Dd + (i - 512)] : 0.f;
    } else {
        int b3 = blk - 4096;
        int l = b3 / 768;
        int i = (b3 % 768) * 256 + tid;        // [0, 196608)
        int s = i >> 16, o = i & 65535;
        const float* src = (s == 0) ? (rw2 + l * Dd * Dd)
                         : ((s == 1) ? (mw1 + l * Dd * Dd) : (mw2 + l * Dd * Dd));
        float v = src[o];
        __nv_bfloat16 h, lo; split_bf16(v, h, lo);
        w2h[l * 3 * Dd * Dd + i] = h;
        w2l[l * 3 * Dd * Dd + i] = lo;
    }
}

// ---------------- attention + gelu aggregation, 4 queries per block ----------------
// qkab row layout: [k(256) | q(256) | a(256) | bb(256)]
__global__ void __launch_bounds__(256)
attn_kernel(const float* __restrict__ qkab,
            __nv_bfloat16* __restrict__ ggh, __nv_bfloat16* __restrict__ ggl)
{
    const int b = blockIdx.y, i0 = blockIdx.x * 4;
    const int tid = threadIdx.x;
    const int lane = tid & 31, warp = tid >> 5;

    __shared__ float sq[4][Dd];
    __shared__ float sa[4][Dd];
    __shared__ float sl[4][Kk];
    __shared__ float sp[4][Kk];

    const float* base = qkab + (size_t)b * Kk * QS;

    #pragma unroll
    for (int ii = 0; ii < 4; ii++) {
        const float* row = base + (size_t)(i0 + ii) * QS;
        sq[ii][tid] = row[256 + tid];
        sa[ii][tid] = row[512 + tid];
    }
    __syncthreads();

    for (int j = warp; j < Kk; j += 8) {
        const float* kj = base + (size_t)j * QS;
        float kv[8];
        #pragma unroll
        for (int m = 0; m < 8; m++) kv[m] = kj[lane + 32 * m];
        #pragma unroll
        for (int ii = 0; ii < 4; ii++) {
            float t = 0.f;
            #pragma unroll
            for (int m = 0; m < 8; m++) t = fmaf(sq[ii][lane + 32 * m], kv[m], t);
            #pragma unroll
            for (int o = 16; o; o >>= 1) t += __shfl_xor_sync(0xffffffffu, t, o);
            if (lane == 0) sl[ii][j] = t * 0.0625f;   // D^-0.5
        }
    }
    __syncthreads();

    if (warp < 4) {
        float v0 = sl[warp][lane], v1 = sl[warp][lane + 32];
        float m = fmaxf(v0, v1);
        #pragma unroll
        for (int o = 16; o; o >>= 1) m = fmaxf(m, __shfl_xor_sync(0xffffffffu, m, o));
        float e0 = __expf(v0 - m), e1 = __expf(v1 - m);
        float s = e0 + e1;
        #pragma unroll
        for (int o = 16; o; o >>= 1) s += __shfl_xor_sync(0xffffffffu, s, o);
        float inv = 1.f / s;
        sp[warp][lane] = e0 * inv; sp[warp][lane + 32] = e1 * inv;
    }
    __syncthreads();

    const float a0 = sa[0][tid], a1 = sa[1][tid], a2 = sa[2][tid], a3 = sa[3][tid];
    float c0 = 0.f, c1 = 0.f, c2 = 0.f, c3 = 0.f;
    const float* bbp = base + 768 + tid;
    #pragma unroll 4
    for (int j = 0; j < Kk; j++) {
        float bb = __ldg(bbp + (size_t)j * QS);
        c0 = fmaf(sp[0][j], gelu_fast(a0 - bb), c0);
        c1 = fmaf(sp[1][j], gelu_fast(a1 - bb), c1);
        c2 = fmaf(sp[2][j], gelu_fast(a2 - bb), c2);
        c3 = fmaf(sp[3][j], gelu_fast(a3 - bb), c3);
    }
    float cc[4] = {c0, c1, c2, c3};
    #pragma unroll
    for (int ii = 0; ii < 4; ii++) {
        size_t idx = (size_t)(b * Kk + i0 + ii) * Dd + tid;
        __nv_bfloat16 h, l; split_bf16(cc[ii], h, l);
        ggh[idx] = h; ggl[idx] = l;
    }
}

// ---------------- layernorm over D=256 -> duals only ----------------
__device__ __forceinline__ float blocksum256(float v, float* red) {
    int lane = threadIdx.x & 31, w = threadIdx.x >> 5;
    #pragma unroll
    for (int o = 16; o; o >>= 1) v += __shfl_xor_sync(0xffffffffu, v, o);
    __syncthreads();
    if (lane == 0) red[w] = v;
    __syncthreads();
    float t = red[0];
    #pragma unroll
    for (int i = 1; i < 8; i++) t += red[i];
    return t;
}

__global__ void __launch_bounds__(256)
ln_kernel(const float* __restrict__ in, const float* __restrict__ gam,
          const float* __restrict__ bet,
          __nv_bfloat16* __restrict__ outh, __nv_bfloat16* __restrict__ outl)
{
    __shared__ float red[8];
    int r = blockIdx.x, tid = threadIdx.x;
    float v = in[r * Dd + tid];
    float mean = blocksum256(v, red) * (1.f / Dd);
    float dv = v - mean;
    float var = blocksum256(dv * dv, red) * (1.f / Dd);
    float o = dv * rsqrtf(var + 1e-5f) * gam[tid] + bet[tid];
    __nv_bfloat16 h, l; split_bf16(o, h, l);
    outh[r * Dd + tid] = h;
    outl[r * Dd + tid] = l;
}

// ---------------- fused pool + heads ----------------
__global__ void __launch_bounds__(256)
pool_head_kernel(const float* __restrict__ x,
                 const float* __restrict__ pw, const float* __restrict__ pb,
                 const float* __restrict__ muw, const float* __restrict__ mub,
                 const float* __restrict__ spw, const float* __restrict__ spb,
                 float* __restrict__ out)
{
    int b = blockIdx.x, tid = threadIdx.x;
    __shared__ float ss[Dd];
    __shared__ float sh[LSs];

    float acc = 0.f;
    #pragma unroll 8
    for (int i = 0; i < Kk; i++) acc += x[(b * Kk + i) * Dd + tid];
    ss[tid] = acc;
    __syncthreads();

    if (tid < LSs) {
        float a = pb[tid];
        #pragma unroll 8
        for (int d = 0; d < Dd; d++) a = fmaf(ss[d], pw[tid * Dd + d], a);
        sh[tid] = 0.5f * a * (1.0f + erff(a * 0.7071067811865476f));
    }
    __syncthreads();

    if (tid < LSs) {
        float mu = mub[tid], sc = spb[tid];
        #pragma unroll 8
        for (int d = 0; d < LSs; d++) {
            mu = fmaf(sh[d], muw[tid * LSs + d], mu);
            sc = fmaf(sh[d], spw[tid * LSs + d], sc);
        }
        float spv = fmaxf(sc, 0.f) + log1pf(expf(-fabsf(sc)));
        out[b * LSs + tid] = mu;
        out[Bb * LSs + b * LSs + tid] = spv;
    }
}

// ---------------- launch ----------------
extern "C" void kernel_launch(void* const* d_in, const int* in_sizes, int n_in,
                              void* d_out, int out_size)
{
    (void)in_sizes; (void)n_in; (void)out_size;
    const float* X    = (const float*)d_in[0];
    const float* k_w  = (const float*)d_in[1];
    const float* q_w  = (const float*)d_in[2];
    const float* rw1  = (const float*)d_in[3];
    const float* rb1  = (const float*)d_in[4];
    const float* rw2  = (const float*)d_in[5];
    const float* rb2  = (const float*)d_in[6];
    const float* lng  = (const float*)d_in[7];
    const float* lnb  = (const float*)d_in[8];
    const float* mw1  = (const float*)d_in[9];
    const float* mb1  = (const float*)d_in[10];
    const float* mw2  = (const float*)d_in[11];
    const float* mb2  = (const float*)d_in[12];
    const float* pw   = (const float*)d_in[13];
    const float* pb   = (const float*)d_in[14];
    const float* muw  = (const float*)d_in[15];
    const float* mub  = (const float*)d_in[16];
    const float* spw  = (const float*)d_in[17];
    const float* spb  = (const float*)d_in[18];
    float* out = (float*)d_out;

    static float *px=nullptr,*pqkab=nullptr,*php=nullptr,*pbc=nullptr;
    static __nv_bfloat16 *pxh,*pxl,*pggh,*pggl,*phh,*phl,*pth,*ptl,*pwch,*pwcl,*pw2h,*pw2l;
    if (!px) {
        cudaGetSymbolAddress((void**)&px,    g_x);
        cudaGetSymbolAddress((void**)&pqkab, g_qkab);
        cudaGetSymbolAddress((void**)&php,   g_hp);
        cudaGetSymbolAddress((void**)&pbc,   g_bc);
        cudaGetSymbolAddress((void**)&pxh,   g_xh);
        cudaGetSymbolAddress((void**)&pxl,   g_xl);
        cudaGetSymbolAddress((void**)&pggh,  g_ggh);
        cudaGetSymbolAddress((void**)&pggl,  g_ggl);
        cudaGetSymbolAddress((void**)&phh,   g_hh);
        cudaGetSymbolAddress((void**)&phl,   g_hl);
        cudaGetSymbolAddress((void**)&pth,   g_th);
        cudaGetSymbolAddress((void**)&ptl,   g_tl);
        cudaGetSymbolAddress((void**)&pwch,  g_wch);
        cudaGetSymbolAddress((void**)&pwcl,  g_wcl);
        cudaGetSymbolAddress((void**)&pw2h,  g_w2h);
        cudaGetSymbolAddress((void**)&pw2l,  g_w2l);
        cudaFuncSetAttribute((const void*)tc_gemm<128, 64, 64, 32>,
                             cudaFuncAttributeMaxDynamicSharedMemorySize, SM_BIG);
        cudaFuncSetAttribute((const void*)tc_gemm<64, 32, 32, 16>,
                             cudaFuncAttributeMaxDynamicSharedMemorySize, SM_SMALL);
    }

    // one fused prep launch: input conversion + all weight packing
    prep_kernel<<<5632, 256>>>(X, k_w, q_w, rw1, rb1, rw2, mw1, mw2,
                               px, pxh, pxl, pwch, pwcl, pbc, pw2h, pw2l);

    for (int l = 0; l < NLl; l++) {
        const float* rb2_l = rb2 + l * Dd;
        const float* lg_l  = lng + l * Dd;
        const float* lb_l  = lnb + l * Dd;
        const float* mb1_l = mb1 + l * Dd;
        const float* mb2_l = mb2 + l * Dd;
        __nv_bfloat16* wch_l = pwch + l * 4 * Dd * Dd;
        __nv_bfloat16* wcl_l = pwcl + l * 4 * Dd * Dd;
        __nv_bfloat16* w2h_l = pw2h + l * 3 * Dd * Dd;
        __nv_bfloat16* w2l_l = pw2l + l * 3 * Dd * Dd;
        float* bc_l = pbc + l * 4 * Dd;

        // fused k|q|a|bb projection: [2048,256] @ [1024,256]^T -> qkab fp32
        tc_gemm<128, 64, 64, 32><<<dim3(16, 16), 128, SM_BIG>>>(
            pxh, pxl, wch_l, wcl_l, bc_l, nullptr, pqkab, QS, nullptr, nullptr, 0);

        attn_kernel<<<dim3(Kk / 4, Bb), 256>>>(pqkab, pggh, pggl);

        // agg proj + residual -> php (fp32)
        tc_gemm<64, 32, 32, 16><<<dim3(8, 32), 128, SM_SMALL>>>(
            pggh, pggl, w2h_l, w2l_l, rb2_l, px, php, Dd, nullptr, nullptr, 0);
        ln_kernel<<<Mm, 256>>>(php, lg_l, lb_l, phh, phl);
        // mlp1 (gelu) -> t duals only
        tc_gemm<64, 32, 32, 16><<<dim3(8, 32), 128, SM_SMALL>>>(
            phh, phl, w2h_l + Dd * Dd, w2l_l + Dd * Dd, mb1_l, nullptr, nullptr, Dd, pth, ptl, 1);
        // mlp2 + residual -> px fp32 + duals
        tc_gemm<64, 32, 32, 16><<<dim3(8, 32), 128, SM_SMALL>>>(
            pth, ptl, w2h_l + 2 * Dd * Dd, w2l_l + 2 * Dd * Dd, mb2_l, px, px, Dd, pxh, pxl, 0);
    }

    pool_head_kernel<<<Bb, 256>>>(px, pw, pb, muw, mub, spw, spb, out);
}